// round 2
// baseline (speedup 1.0000x reference)
#include <cuda_runtime.h>
#include <cuda_bf16.h>
#include <math.h>

// ---------------------------------------------------------------------------
// Problem constants
// ---------------------------------------------------------------------------
#define BATCH 1024
#define SEQ   64
#define EMB   1024
#define NH    16
#define HD    64
#define HC    32     // smolgen compress channels
#define HS    256    // smolgen hidden
#define GS    256    // smolgen gen size
#define LN_EPS 1e-3f

// ---------------------------------------------------------------------------
// Scratch (device globals -- no cudaMalloc allowed)
// ---------------------------------------------------------------------------
__device__ float g_Q   [BATCH * NH * SEQ * HD];   // (B,H,S,HD)
__device__ float g_K   [BATCH * NH * SEQ * HD];
__device__ float g_V   [BATCH * NH * SEQ * HD];
__device__ float g_COMP[BATCH * SEQ * HC];        // (B, S*HC) = (B,2048)
__device__ float g_T1  [BATCH * HS];              // pre-act dense1
__device__ float g_HID [BATCH * HS];
__device__ float g_T2  [BATCH * GS * NH];         // pre-act dense2
__device__ float g_GEN [BATCH * GS * NH];
__device__ float g_BIAS[BATCH * NH * SEQ * SEQ];  // (B,H,S,S)
__device__ float g_ATT [BATCH * SEQ * EMB];       // (B,S,E)

// Scratch selector so host code never needs cudaGetSymbolAddress.
__device__ __forceinline__ float* scratch_ptr(int which) {
    switch (which) {
        case 0: return g_Q;
        case 1: return g_K;
        case 2: return g_V;
        case 3: return g_COMP;
        case 4: return g_T1;
        case 5: return g_HID;
        case 6: return g_T2;
        case 7: return g_GEN;
        case 8: return g_BIAS;
        default: return g_ATT;
    }
}

// ---------------------------------------------------------------------------
// Generic SGEMM: C[M,N] = A[M,K] @ B[K,N] (+ bias[N])
// Requires M%128==0, N%128==0, K%16==0.
// srcC >= 0: A comes from scratch_ptr(srcC). dst >= 0: C goes to scratch.
// mode 0: row-major output.  mode 1: QKV scatter to (B,H,S,HD).
// ---------------------------------------------------------------------------
#define BM 128
#define BN 128
#define BKK 16

__global__ __launch_bounds__(256) void sgemm_kernel(
    const float* __restrict__ Ain, const float* __restrict__ Bw,
    const float* __restrict__ bias, float* __restrict__ Cout,
    int M, int N, int K, int mode, int srcA, int dstC)
{
    const float* A = (srcA >= 0) ? scratch_ptr(srcA) : Ain;
    float* C = (dstC >= 0) ? scratch_ptr(dstC) : Cout;

    __shared__ float As[BKK][BM];
    __shared__ float Bs[BKK][BN];

    const int tid = threadIdx.x;
    const int bx = blockIdx.x, by = blockIdx.y;
    const int tx = tid & 15;        // 0..15 -> col group
    const int ty = tid >> 4;        // 0..15 -> row group

    const float* Ab = A + (size_t)by * BM * K;
    const float* Bb = Bw + (size_t)bx * BN;

    const int arow = tid >> 2;            // 0..63
    const int acol = (tid & 3) * 4;       // 0,4,8,12
    const int brow = tid >> 5;            // 0..7
    const int bcol = (tid & 31) * 4;      // 0..124

    float acc[8][8];
    #pragma unroll
    for (int i = 0; i < 8; i++)
        #pragma unroll
        for (int j = 0; j < 8; j++) acc[i][j] = 0.f;

    for (int k0 = 0; k0 < K; k0 += BKK) {
        float4 a0 = *(const float4*)(Ab + (size_t)arow * K + k0 + acol);
        float4 a1 = *(const float4*)(Ab + (size_t)(arow + 64) * K + k0 + acol);
        As[acol + 0][arow] = a0.x;
        As[acol + 1][arow] = a0.y;
        As[acol + 2][arow] = a0.z;
        As[acol + 3][arow] = a0.w;
        As[acol + 0][arow + 64] = a1.x;
        As[acol + 1][arow + 64] = a1.y;
        As[acol + 2][arow + 64] = a1.z;
        As[acol + 3][arow + 64] = a1.w;

        float4 b0 = *(const float4*)(Bb + (size_t)(k0 + brow) * N + bcol);
        float4 b1 = *(const float4*)(Bb + (size_t)(k0 + brow + 8) * N + bcol);
        *(float4*)&Bs[brow][bcol]     = b0;
        *(float4*)&Bs[brow + 8][bcol] = b1;

        __syncthreads();

        #pragma unroll
        for (int kk = 0; kk < BKK; kk++) {
            float4 a04 = *(const float4*)&As[kk][ty * 8];
            float4 a14 = *(const float4*)&As[kk][ty * 8 + 4];
            float4 b04 = *(const float4*)&Bs[kk][tx * 8];
            float4 b14 = *(const float4*)&Bs[kk][tx * 8 + 4];
            float ar[8] = {a04.x, a04.y, a04.z, a04.w, a14.x, a14.y, a14.z, a14.w};
            float br[8] = {b04.x, b04.y, b04.z, b04.w, b14.x, b14.y, b14.z, b14.w};
            #pragma unroll
            for (int i = 0; i < 8; i++)
                #pragma unroll
                for (int j = 0; j < 8; j++)
                    acc[i][j] += ar[i] * br[j];
        }
        __syncthreads();
    }

    // bias for the 8 columns handled by this thread
    const int n0 = bx * BN + tx * 8;
    float bv[8];
    #pragma unroll
    for (int j = 0; j < 8; j++) bv[j] = bias ? bias[n0 + j] : 0.f;

    if (mode == 0) {
        #pragma unroll
        for (int i = 0; i < 8; i++) {
            const int row = by * BM + ty * 8 + i;
            float* cp = C + (size_t)row * N + n0;
            float4 o0 = make_float4(acc[i][0] + bv[0], acc[i][1] + bv[1],
                                    acc[i][2] + bv[2], acc[i][3] + bv[3]);
            float4 o1 = make_float4(acc[i][4] + bv[4], acc[i][5] + bv[5],
                                    acc[i][6] + bv[6], acc[i][7] + bv[7]);
            *(float4*)cp       = o0;
            *(float4*)(cp + 4) = o1;
        }
    } else {
        // scatter: row m=(b,s), col n=(h,d)  ->  out[((b*NH+h)*SEQ+s)*HD+d]
        const int h  = n0 >> 6;
        const int d0 = n0 & 63;
        #pragma unroll
        for (int i = 0; i < 8; i++) {
            const int m = by * BM + ty * 8 + i;
            const int b = m >> 6, s = m & 63;
            float* cp = C + (((size_t)(b * NH + h) * SEQ + s) * HD) + d0;
            float4 o0 = make_float4(acc[i][0] + bv[0], acc[i][1] + bv[1],
                                    acc[i][2] + bv[2], acc[i][3] + bv[3]);
            float4 o1 = make_float4(acc[i][4] + bv[4], acc[i][5] + bv[5],
                                    acc[i][6] + bv[6], acc[i][7] + bv[7]);
            *(float4*)cp       = o0;
            *(float4*)(cp + 4) = o1;
        }
    }
}

// ---------------------------------------------------------------------------
// Compress: x(B,S,E) @ Wc(E,HC) -> g_COMP(B, S*HC)  (no bias)
// One block per batch element; K chunked through smem.
// ---------------------------------------------------------------------------
__global__ __launch_bounds__(256) void compress_kernel(
    const float* __restrict__ x, const float* __restrict__ Wc)
{
    __shared__ float xs[64][64];   // (s, k-chunk)
    __shared__ float wc[64][32];   // (k-chunk, c)

    const int b = blockIdx.x;
    const int tid = threadIdx.x;
    const int c = tid & 31;
    const int s0 = tid >> 5;       // warp id 0..7

    const float* xb = x + (size_t)b * SEQ * EMB;
    float acc[8];
    #pragma unroll
    for (int r = 0; r < 8; r++) acc[r] = 0.f;

    for (int kc = 0; kc < EMB; kc += 64) {
        #pragma unroll
        for (int p = 0; p < 4; p++) {
            int idx = tid + 256 * p;          // 0..1023 float4s
            int s = idx >> 4, k4 = (idx & 15) * 4;
            *(float4*)&xs[s][k4] = *(const float4*)(xb + (size_t)s * EMB + kc + k4);
        }
        #pragma unroll
        for (int p = 0; p < 2; p++) {
            int idx = tid + 256 * p;          // 0..511 float4s
            int k = idx >> 3, c4 = (idx & 7) * 4;
            *(float4*)&wc[k][c4] = *(const float4*)(Wc + (size_t)(kc + k) * HC + c4);
        }
        __syncthreads();
        #pragma unroll
        for (int k = 0; k < 64; k++) {
            float wv = wc[k][c];
            #pragma unroll
            for (int r = 0; r < 8; r++)
                acc[r] += xs[s0 * 8 + r][k] * wv;
        }
        __syncthreads();
    }
    #pragma unroll
    for (int r = 0; r < 8; r++)
        g_COMP[(size_t)b * (SEQ * HC) + (s0 * 8 + r) * HC + c] = acc[r];
}

// ---------------------------------------------------------------------------
// silu + LayerNorm over last dim: out = LN(silu(in)) * g + be
// One block per row; in/out selected from scratch. N <= 4096.
// ---------------------------------------------------------------------------
__global__ __launch_bounds__(256) void silu_ln_kernel(
    const float* __restrict__ g, const float* __restrict__ be,
    int N, int srcIdx, int dstIdx)
{
    const float* in = scratch_ptr(srcIdx);
    float* out = scratch_ptr(dstIdx);

    __shared__ float hs[4096];
    __shared__ float red[2][8];

    const int row = blockIdx.x;
    const int tid = threadIdx.x;
    const float* pin = in + (size_t)row * N;

    float sum = 0.f, sq = 0.f;
    for (int i = tid; i < N; i += 256) {
        float y = pin[i];
        float h = y / (1.f + expf(-y));    // silu
        hs[i] = h;
        sum += h;
        sq  += h * h;
    }
    #pragma unroll
    for (int off = 16; off > 0; off >>= 1) {
        sum += __shfl_xor_sync(0xffffffffu, sum, off);
        sq  += __shfl_xor_sync(0xffffffffu, sq,  off);
    }
    if ((tid & 31) == 0) { red[0][tid >> 5] = sum; red[1][tid >> 5] = sq; }
    __syncthreads();
    if (tid < 32) {
        float s = (tid < 8) ? red[0][tid] : 0.f;
        float q = (tid < 8) ? red[1][tid] : 0.f;
        #pragma unroll
        for (int off = 4; off > 0; off >>= 1) {
            s += __shfl_xor_sync(0xffffffffu, s, off);
            q += __shfl_xor_sync(0xffffffffu, q, off);
        }
        if (tid == 0) { red[0][0] = s; red[1][0] = q; }
    }
    __syncthreads();
    const float mean = red[0][0] / (float)N;
    const float var  = red[1][0] / (float)N - mean * mean;
    const float inv  = rsqrtf(var + LN_EPS);

    for (int i = tid; i < N; i += 256)
        out[(size_t)row * N + i] = (hs[i] - mean) * inv * g[i] + be[i];
}

// ---------------------------------------------------------------------------
// Attention: per (b,h): softmax(q@k^T * scale + bias) @ v
// Q/K/V in (B,H,S,HD) device globals; Out written to g_ATT (B,S,E).
// One block per (b,h).
// ---------------------------------------------------------------------------
__global__ __launch_bounds__(256) void attn_kernel()
{
    __shared__ float ks[64][65];
    __shared__ float vs[64][65];
    __shared__ float ps[8][64];

    const int bh = blockIdx.x;
    const int b = bh >> 4, h = bh & 15;
    const int tid = threadIdx.x;
    const float* kp = g_K + (size_t)bh * (SEQ * HD);
    const float* vp = g_V + (size_t)bh * (SEQ * HD);
    const float* qp = g_Q + (size_t)bh * (SEQ * HD);
    const float* bp = g_BIAS + (size_t)bh * (SEQ * SEQ);

    #pragma unroll
    for (int p = 0; p < 4; p++) {
        int idx = tid + 256 * p;             // 1024 float4 per tensor
        int s = idx >> 4, d4 = (idx & 15) * 4;
        float4 kv = *(const float4*)(kp + s * HD + d4);
        ks[s][d4] = kv.x; ks[s][d4 + 1] = kv.y; ks[s][d4 + 2] = kv.z; ks[s][d4 + 3] = kv.w;
        float4 vv = *(const float4*)(vp + s * HD + d4);
        vs[s][d4] = vv.x; vs[s][d4 + 1] = vv.y; vs[s][d4 + 2] = vv.z; vs[s][d4 + 3] = vv.w;
    }
    __syncthreads();

    const int w = tid >> 5, lane = tid & 31;
    const float scale = 0.125f;   // 64^-0.5

    for (int r = w * 8; r < w * 8 + 8; r++) {
        const float* q = qp + r * HD;
        float dot0 = 0.f, dot1 = 0.f;
        #pragma unroll
        for (int k = 0; k < 64; k++) {
            float qk = __ldg(q + k);
            dot0 += qk * ks[lane][k];
            dot1 += qk * ks[lane + 32][k];
        }
        float acc0 = dot0 * scale + bp[r * 64 + lane];
        float acc1 = dot1 * scale + bp[r * 64 + lane + 32];

        float m = fmaxf(acc0, acc1);
        #pragma unroll
        for (int off = 16; off > 0; off >>= 1)
            m = fmaxf(m, __shfl_xor_sync(0xffffffffu, m, off));
        float e0 = __expf(acc0 - m), e1 = __expf(acc1 - m);
        float s = e0 + e1;
        #pragma unroll
        for (int off = 16; off > 0; off >>= 1)
            s += __shfl_xor_sync(0xffffffffu, s, off);
        float invs = 1.f / s;

        __syncwarp();
        ps[w][lane]      = e0 * invs;
        ps[w][lane + 32] = e1 * invs;
        __syncwarp();

        float o0 = 0.f, o1 = 0.f;
        #pragma unroll
        for (int j = 0; j < 64; j++) {
            float pj = ps[w][j];
            o0 += pj * vs[j][lane];
            o1 += pj * vs[j][lane + 32];
        }
        float* op = g_ATT + ((size_t)(b * SEQ + r) * EMB) + h * HD;
        op[lane]      = o0;
        op[lane + 32] = o1;
    }
}

// ---------------------------------------------------------------------------
// kernel_launch : launches only (graph-capture safe; no runtime API calls)
// ---------------------------------------------------------------------------
extern "C" void kernel_launch(void* const* d_in, const int* in_sizes, int n_in,
                              void* d_out, int out_size)
{
    const float* x   = (const float*)d_in[0];
    const float* Wq  = (const float*)d_in[1];
    const float* bq  = (const float*)d_in[2];
    const float* Wk  = (const float*)d_in[3];
    const float* bk  = (const float*)d_in[4];
    const float* Wv  = (const float*)d_in[5];
    const float* bv  = (const float*)d_in[6];
    const float* Wo  = (const float*)d_in[7];
    const float* bo  = (const float*)d_in[8];
    const float* Wc  = (const float*)d_in[9];
    const float* Wd1 = (const float*)d_in[10];
    const float* bd1 = (const float*)d_in[11];
    const float* g1  = (const float*)d_in[12];
    const float* be1 = (const float*)d_in[13];
    const float* Wd2 = (const float*)d_in[14];
    const float* bd2 = (const float*)d_in[15];
    const float* g2  = (const float*)d_in[16];
    const float* be2 = (const float*)d_in[17];
    const float* Wg  = (const float*)d_in[18];

    const int MROWS = BATCH * SEQ;   // 65536

    // QKV projections (A = x input, C scattered into g_Q/g_K/g_V)
    sgemm_kernel<<<dim3(EMB / BN, MROWS / BM), 256>>>(x, Wq, bq, nullptr, MROWS, EMB, EMB, 1, -1, 0);
    sgemm_kernel<<<dim3(EMB / BN, MROWS / BM), 256>>>(x, Wk, bk, nullptr, MROWS, EMB, EMB, 1, -1, 1);
    sgemm_kernel<<<dim3(EMB / BN, MROWS / BM), 256>>>(x, Wv, bv, nullptr, MROWS, EMB, EMB, 1, -1, 2);

    // Smolgen
    compress_kernel<<<BATCH, 256>>>(x, Wc);
    sgemm_kernel<<<dim3(HS / BN, BATCH / BM), 256>>>(nullptr, Wd1, bd1, nullptr,
                                                     BATCH, HS, SEQ * HC, 0, 3, 4);
    silu_ln_kernel<<<BATCH, 256>>>(g1, be1, HS, 4, 5);
    sgemm_kernel<<<dim3((GS * NH) / BN, BATCH / BM), 256>>>(nullptr, Wd2, bd2, nullptr,
                                                            BATCH, GS * NH, HS, 0, 5, 6);
    silu_ln_kernel<<<BATCH, 256>>>(g2, be2, GS * NH, 6, 7);
    // gen (B*H, GS) @ Wg (GS, S*S) -> bias (B*H, S*S)
    sgemm_kernel<<<dim3((SEQ * SEQ) / BN, (BATCH * NH) / BM), 256>>>(
        nullptr, Wg, nullptr, nullptr, BATCH * NH, SEQ * SEQ, GS, 0, 7, 8);

    // Attention
    attn_kernel<<<BATCH * NH, 256>>>();

    // Output projection: A = g_ATT, C = d_out
    sgemm_kernel<<<dim3(EMB / BN, MROWS / BM), 256>>>(nullptr, Wo, bo, (float*)d_out,
                                                      MROWS, EMB, EMB, 0, 9, -1);
}

// round 4
// speedup vs baseline: 1.0010x; 1.0010x over previous
#include <cuda_runtime.h>
#include <cuda_bf16.h>
#include <math.h>

// ---------------------------------------------------------------------------
// Problem constants
// ---------------------------------------------------------------------------
#define BATCH 1024
#define SEQ   64
#define EMB   1024
#define NH    16
#define HD    64
#define HC    32     // smolgen compress channels
#define HS    256    // smolgen hidden
#define GS    256    // smolgen gen size
#define LN_EPS 1e-3f

// ---------------------------------------------------------------------------
// Scratch (device globals -- no cudaMalloc allowed)
// ---------------------------------------------------------------------------
__device__ float g_Q   [BATCH * NH * SEQ * HD];   // (B,H,S,HD)
__device__ float g_K   [BATCH * NH * SEQ * HD];
__device__ float g_V   [BATCH * NH * SEQ * HD];
__device__ float g_COMP[BATCH * SEQ * HC];        // (B, S*HC) = (B,2048)
__device__ float g_T1  [BATCH * HS];              // pre-act dense1
__device__ float g_HID [BATCH * HS];
__device__ float g_T2  [BATCH * GS * NH];         // pre-act dense2
__device__ float g_GEN [BATCH * GS * NH];
__device__ float g_BIAS[BATCH * NH * SEQ * SEQ];  // (B,H,S,S)
__device__ float g_ATT [BATCH * SEQ * EMB];       // (B,S,E)

// Scratch selector so host code never needs cudaGetSymbolAddress.
__device__ __forceinline__ float* scratch_ptr(int which) {
    switch (which) {
        case 0: return g_Q;
        case 1: return g_K;
        case 2: return g_V;
        case 3: return g_COMP;
        case 4: return g_T1;
        case 5: return g_HID;
        case 6: return g_T2;
        case 7: return g_GEN;
        case 8: return g_BIAS;
        default: return g_ATT;
    }
}

// ---------------------------------------------------------------------------
// Generic SGEMM: C[M,N] = A[M,K] @ B[K,N] (+ bias[N])
// Requires M%128==0, N%128==0, K%16==0.
// srcC >= 0: A comes from scratch_ptr(srcC). dst >= 0: C goes to scratch.
// mode 0: row-major output.  mode 1: QKV scatter to (B,H,S,HD).
// ---------------------------------------------------------------------------
#define BM 128
#define BN 128
#define BKK 16

__global__ __launch_bounds__(256) void sgemm_kernel(
    const float* __restrict__ Ain, const float* __restrict__ Bw,
    const float* __restrict__ bias, float* __restrict__ Cout,
    int M, int N, int K, int mode, int srcA, int dstC)
{
    const float* A = (srcA >= 0) ? scratch_ptr(srcA) : Ain;
    float* C = (dstC >= 0) ? scratch_ptr(dstC) : Cout;

    __shared__ float As[BKK][BM];
    __shared__ float Bs[BKK][BN];

    const int tid = threadIdx.x;
    const int bx = blockIdx.x, by = blockIdx.y;
    const int tx = tid & 15;        // 0..15 -> col group
    const int ty = tid >> 4;        // 0..15 -> row group

    const float* Ab = A + (size_t)by * BM * K;
    const float* Bb = Bw + (size_t)bx * BN;

    const int arow = tid >> 2;            // 0..63
    const int acol = (tid & 3) * 4;       // 0,4,8,12
    const int brow = tid >> 5;            // 0..7
    const int bcol = (tid & 31) * 4;      // 0..124

    float acc[8][8];
    #pragma unroll
    for (int i = 0; i < 8; i++)
        #pragma unroll
        for (int j = 0; j < 8; j++) acc[i][j] = 0.f;

    for (int k0 = 0; k0 < K; k0 += BKK) {
        float4 a0 = *(const float4*)(Ab + (size_t)arow * K + k0 + acol);
        float4 a1 = *(const float4*)(Ab + (size_t)(arow + 64) * K + k0 + acol);
        As[acol + 0][arow] = a0.x;
        As[acol + 1][arow] = a0.y;
        As[acol + 2][arow] = a0.z;
        As[acol + 3][arow] = a0.w;
        As[acol + 0][arow + 64] = a1.x;
        As[acol + 1][arow + 64] = a1.y;
        As[acol + 2][arow + 64] = a1.z;
        As[acol + 3][arow + 64] = a1.w;

        float4 b0 = *(const float4*)(Bb + (size_t)(k0 + brow) * N + bcol);
        float4 b1 = *(const float4*)(Bb + (size_t)(k0 + brow + 8) * N + bcol);
        *(float4*)&Bs[brow][bcol]     = b0;
        *(float4*)&Bs[brow + 8][bcol] = b1;

        __syncthreads();

        #pragma unroll
        for (int kk = 0; kk < BKK; kk++) {
            float4 a04 = *(const float4*)&As[kk][ty * 8];
            float4 a14 = *(const float4*)&As[kk][ty * 8 + 4];
            float4 b04 = *(const float4*)&Bs[kk][tx * 8];
            float4 b14 = *(const float4*)&Bs[kk][tx * 8 + 4];
            float ar[8] = {a04.x, a04.y, a04.z, a04.w, a14.x, a14.y, a14.z, a14.w};
            float br[8] = {b04.x, b04.y, b04.z, b04.w, b14.x, b14.y, b14.z, b14.w};
            #pragma unroll
            for (int i = 0; i < 8; i++)
                #pragma unroll
                for (int j = 0; j < 8; j++)
                    acc[i][j] += ar[i] * br[j];
        }
        __syncthreads();
    }

    // bias for the 8 columns handled by this thread
    const int n0 = bx * BN + tx * 8;
    float bv[8];
    #pragma unroll
    for (int j = 0; j < 8; j++) bv[j] = bias ? bias[n0 + j] : 0.f;

    if (mode == 0) {
        #pragma unroll
        for (int i = 0; i < 8; i++) {
            const int row = by * BM + ty * 8 + i;
            float* cp = C + (size_t)row * N + n0;
            float4 o0 = make_float4(acc[i][0] + bv[0], acc[i][1] + bv[1],
                                    acc[i][2] + bv[2], acc[i][3] + bv[3]);
            float4 o1 = make_float4(acc[i][4] + bv[4], acc[i][5] + bv[5],
                                    acc[i][6] + bv[6], acc[i][7] + bv[7]);
            *(float4*)cp       = o0;
            *(float4*)(cp + 4) = o1;
        }
    } else {
        // scatter: row m=(b,s), col n=(h,d)  ->  out[((b*NH+h)*SEQ+s)*HD+d]
        const int h  = n0 >> 6;
        const int d0 = n0 & 63;
        #pragma unroll
        for (int i = 0; i < 8; i++) {
            const int m = by * BM + ty * 8 + i;
            const int b = m >> 6, s = m & 63;
            float* cp = C + (((size_t)(b * NH + h) * SEQ + s) * HD) + d0;
            float4 o0 = make_float4(acc[i][0] + bv[0], acc[i][1] + bv[1],
                                    acc[i][2] + bv[2], acc[i][3] + bv[3]);
            float4 o1 = make_float4(acc[i][4] + bv[4], acc[i][5] + bv[5],
                                    acc[i][6] + bv[6], acc[i][7] + bv[7]);
            *(float4*)cp       = o0;
            *(float4*)(cp + 4) = o1;
        }
    }
}

// ---------------------------------------------------------------------------
// Compress: x(B,S,E) @ Wc(E,HC) -> g_COMP(B, S*HC)  (no bias)
// One block per batch element; K chunked through smem.
// ---------------------------------------------------------------------------
__global__ __launch_bounds__(256) void compress_kernel(
    const float* __restrict__ x, const float* __restrict__ Wc)
{
    __shared__ float xs[64][64];   // (s, k-chunk)
    __shared__ float wc[64][32];   // (k-chunk, c)

    const int b = blockIdx.x;
    const int tid = threadIdx.x;
    const int c = tid & 31;
    const int s0 = tid >> 5;       // warp id 0..7

    const float* xb = x + (size_t)b * SEQ * EMB;
    float acc[8];
    #pragma unroll
    for (int r = 0; r < 8; r++) acc[r] = 0.f;

    for (int kc = 0; kc < EMB; kc += 64) {
        #pragma unroll
        for (int p = 0; p < 4; p++) {
            int idx = tid + 256 * p;          // 0..1023 float4s
            int s = idx >> 4, k4 = (idx & 15) * 4;
            *(float4*)&xs[s][k4] = *(const float4*)(xb + (size_t)s * EMB + kc + k4);
        }
        #pragma unroll
        for (int p = 0; p < 2; p++) {
            int idx = tid + 256 * p;          // 0..511 float4s
            int k = idx >> 3, c4 = (idx & 7) * 4;
            *(float4*)&wc[k][c4] = *(const float4*)(Wc + (size_t)(kc + k) * HC + c4);
        }
        __syncthreads();
        #pragma unroll
        for (int k = 0; k < 64; k++) {
            float wv = wc[k][c];
            #pragma unroll
            for (int r = 0; r < 8; r++)
                acc[r] += xs[s0 * 8 + r][k] * wv;
        }
        __syncthreads();
    }
    #pragma unroll
    for (int r = 0; r < 8; r++)
        g_COMP[(size_t)b * (SEQ * HC) + (s0 * 8 + r) * HC + c] = acc[r];
}

// ---------------------------------------------------------------------------
// silu + LayerNorm over last dim: out = LN(silu(in)) * g + be
// One block per row; in/out selected from scratch. N <= 4096.
// ---------------------------------------------------------------------------
__global__ __launch_bounds__(256) void silu_ln_kernel(
    const float* __restrict__ g, const float* __restrict__ be,
    int N, int srcIdx, int dstIdx)
{
    const float* in = scratch_ptr(srcIdx);
    float* out = scratch_ptr(dstIdx);

    __shared__ float hs[4096];
    __shared__ float red[2][8];

    const int row = blockIdx.x;
    const int tid = threadIdx.x;
    const float* pin = in + (size_t)row * N;

    float sum = 0.f, sq = 0.f;
    for (int i = tid; i < N; i += 256) {
        float y = pin[i];
        float h = y / (1.f + expf(-y));    // silu
        hs[i] = h;
        sum += h;
        sq  += h * h;
    }
    #pragma unroll
    for (int off = 16; off > 0; off >>= 1) {
        sum += __shfl_xor_sync(0xffffffffu, sum, off);
        sq  += __shfl_xor_sync(0xffffffffu, sq,  off);
    }
    if ((tid & 31) == 0) { red[0][tid >> 5] = sum; red[1][tid >> 5] = sq; }
    __syncthreads();
    if (tid < 32) {
        float s = (tid < 8) ? red[0][tid] : 0.f;
        float q = (tid < 8) ? red[1][tid] : 0.f;
        #pragma unroll
        for (int off = 4; off > 0; off >>= 1) {
            s += __shfl_xor_sync(0xffffffffu, s, off);
            q += __shfl_xor_sync(0xffffffffu, q, off);
        }
        if (tid == 0) { red[0][0] = s; red[1][0] = q; }
    }
    __syncthreads();
    const float mean = red[0][0] / (float)N;
    const float var  = red[1][0] / (float)N - mean * mean;
    const float inv  = rsqrtf(var + LN_EPS);

    for (int i = tid; i < N; i += 256)
        out[(size_t)row * N + i] = (hs[i] - mean) * inv * g[i] + be[i];
}

// ---------------------------------------------------------------------------
// Attention: per (b,h): softmax(q@k^T * scale + bias) @ v
// Q/K/V in (B,H,S,HD) device globals; Out written to g_ATT (B,S,E).
// One block per (b,h).
// ---------------------------------------------------------------------------
__global__ __launch_bounds__(256) void attn_kernel()
{
    __shared__ float ks[64][65];
    __shared__ float vs[64][65];
    __shared__ float ps[8][64];

    const int bh = blockIdx.x;
    const int b = bh >> 4, h = bh & 15;
    const int tid = threadIdx.x;
    const float* kp = g_K + (size_t)bh * (SEQ * HD);
    const float* vp = g_V + (size_t)bh * (SEQ * HD);
    const float* qp = g_Q + (size_t)bh * (SEQ * HD);
    const float* bp = g_BIAS + (size_t)bh * (SEQ * SEQ);

    #pragma unroll
    for (int p = 0; p < 4; p++) {
        int idx = tid + 256 * p;             // 1024 float4 per tensor
        int s = idx >> 4, d4 = (idx & 15) * 4;
        float4 kv = *(const float4*)(kp + s * HD + d4);
        ks[s][d4] = kv.x; ks[s][d4 + 1] = kv.y; ks[s][d4 + 2] = kv.z; ks[s][d4 + 3] = kv.w;
        float4 vv = *(const float4*)(vp + s * HD + d4);
        vs[s][d4] = vv.x; vs[s][d4 + 1] = vv.y; vs[s][d4 + 2] = vv.z; vs[s][d4 + 3] = vv.w;
    }
    __syncthreads();

    const int w = tid >> 5, lane = tid & 31;
    const float scale = 0.125f;   // 64^-0.5

    for (int r = w * 8; r < w * 8 + 8; r++) {
        const float* q = qp + r * HD;
        float dot0 = 0.f, dot1 = 0.f;
        #pragma unroll
        for (int k = 0; k < 64; k++) {
            float qk = __ldg(q + k);
            dot0 += qk * ks[lane][k];
            dot1 += qk * ks[lane + 32][k];
        }
        float acc0 = dot0 * scale + bp[r * 64 + lane];
        float acc1 = dot1 * scale + bp[r * 64 + lane + 32];

        float m = fmaxf(acc0, acc1);
        #pragma unroll
        for (int off = 16; off > 0; off >>= 1)
            m = fmaxf(m, __shfl_xor_sync(0xffffffffu, m, off));
        float e0 = __expf(acc0 - m), e1 = __expf(acc1 - m);
        float s = e0 + e1;
        #pragma unroll
        for (int off = 16; off > 0; off >>= 1)
            s += __shfl_xor_sync(0xffffffffu, s, off);
        float invs = 1.f / s;

        __syncwarp();
        ps[w][lane]      = e0 * invs;
        ps[w][lane + 32] = e1 * invs;
        __syncwarp();

        float o0 = 0.f, o1 = 0.f;
        #pragma unroll
        for (int j = 0; j < 64; j++) {
            float pj = ps[w][j];
            o0 += pj * vs[j][lane];
            o1 += pj * vs[j][lane + 32];
        }
        float* op = g_ATT + ((size_t)(b * SEQ + r) * EMB) + h * HD;
        op[lane]      = o0;
        op[lane + 32] = o1;
    }
}

// ---------------------------------------------------------------------------
// kernel_launch : launches only (graph-capture safe; no runtime API calls)
// ---------------------------------------------------------------------------
extern "C" void kernel_launch(void* const* d_in, const int* in_sizes, int n_in,
                              void* d_out, int out_size)
{
    const float* x   = (const float*)d_in[0];
    const float* Wq  = (const float*)d_in[1];
    const float* bq  = (const float*)d_in[2];
    const float* Wk  = (const float*)d_in[3];
    const float* bk  = (const float*)d_in[4];
    const float* Wv  = (const float*)d_in[5];
    const float* bv  = (const float*)d_in[6];
    const float* Wo  = (const float*)d_in[7];
    const float* bo  = (const float*)d_in[8];
    const float* Wc  = (const float*)d_in[9];
    const float* Wd1 = (const float*)d_in[10];
    const float* bd1 = (const float*)d_in[11];
    const float* g1  = (const float*)d_in[12];
    const float* be1 = (const float*)d_in[13];
    const float* Wd2 = (const float*)d_in[14];
    const float* bd2 = (const float*)d_in[15];
    const float* g2  = (const float*)d_in[16];
    const float* be2 = (const float*)d_in[17];
    const float* Wg  = (const float*)d_in[18];

    const int MROWS = BATCH * SEQ;   // 65536

    // QKV projections (A = x input, C scattered into g_Q/g_K/g_V)
    sgemm_kernel<<<dim3(EMB / BN, MROWS / BM), 256>>>(x, Wq, bq, nullptr, MROWS, EMB, EMB, 1, -1, 0);
    sgemm_kernel<<<dim3(EMB / BN, MROWS / BM), 256>>>(x, Wk, bk, nullptr, MROWS, EMB, EMB, 1, -1, 1);
    sgemm_kernel<<<dim3(EMB / BN, MROWS / BM), 256>>>(x, Wv, bv, nullptr, MROWS, EMB, EMB, 1, -1, 2);

    // Smolgen
    compress_kernel<<<BATCH, 256>>>(x, Wc);
    sgemm_kernel<<<dim3(HS / BN, BATCH / BM), 256>>>(nullptr, Wd1, bd1, nullptr,
                                                     BATCH, HS, SEQ * HC, 0, 3, 4);
    silu_ln_kernel<<<BATCH, 256>>>(g1, be1, HS, 4, 5);
    sgemm_kernel<<<dim3((GS * NH) / BN, BATCH / BM), 256>>>(nullptr, Wd2, bd2, nullptr,
                                                            BATCH, GS * NH, HS, 0, 5, 6);
    silu_ln_kernel<<<BATCH, 256>>>(g2, be2, GS * NH, 6, 7);
    // gen (B*H, GS) @ Wg (GS, S*S) -> bias (B*H, S*S)
    sgemm_kernel<<<dim3((SEQ * SEQ) / BN, (BATCH * NH) / BM), 256>>>(
        nullptr, Wg, nullptr, nullptr, BATCH * NH, SEQ * SEQ, GS, 0, 7, 8);

    // Attention
    attn_kernel<<<BATCH * NH, 256>>>();

    // Output projection: A = g_ATT, C = d_out
    sgemm_kernel<<<dim3(EMB / BN, MROWS / BM), 256>>>(nullptr, Wo, bo, (float*)d_out,
                                                      MROWS, EMB, EMB, 0, 9, -1);
}

// round 6
// speedup vs baseline: 1.6619x; 1.6603x over previous
#include <cuda_runtime.h>
#include <cuda_bf16.h>
#include <math.h>

typedef unsigned int u32;

// ---------------------------------------------------------------------------
// Problem constants
// ---------------------------------------------------------------------------
#define BATCH 1024
#define SEQ   64
#define EMB   1024
#define NH    16
#define HD    64
#define HC    32
#define HS    256
#define GS    256
#define LN_EPS 1e-3f

// ---------------------------------------------------------------------------
// Scratch (device globals -- no cudaMalloc allowed)
// ---------------------------------------------------------------------------
__device__ float g_Q   [BATCH * NH * SEQ * HD];
__device__ float g_K   [BATCH * NH * SEQ * HD];
__device__ float g_V   [BATCH * NH * SEQ * HD];
__device__ float g_COMP[BATCH * SEQ * HC];
__device__ float g_T1  [BATCH * HS];
__device__ float g_HID [BATCH * HS];
__device__ float g_T2  [BATCH * GS * NH];
__device__ float g_GEN [BATCH * GS * NH];
__device__ float g_BIAS[BATCH * NH * SEQ * SEQ];
__device__ float g_ATT [BATCH * SEQ * EMB];

__device__ __forceinline__ float* scratch_ptr(int which) {
    switch (which) {
        case 0: return g_Q;    case 1: return g_K;   case 2: return g_V;
        case 3: return g_COMP; case 4: return g_T1;  case 5: return g_HID;
        case 6: return g_T2;   case 7: return g_GEN; case 8: return g_BIAS;
        default: return g_ATT;
    }
}

// ---------------------------------------------------------------------------
// HMMA helpers (sm_80+ instructions; legal under compute_100)
// ---------------------------------------------------------------------------
__device__ __forceinline__ u32 smem_u32(const void* p) {
    u32 a;
    asm("{ .reg .u64 t; cvta.to.shared.u64 t, %1; cvt.u32.u64 %0, t; }" : "=r"(a) : "l"(p));
    return a;
}
__device__ __forceinline__ void ldsm_x4(u32* r, u32 addr) {
    asm volatile("ldmatrix.sync.aligned.m8n8.x4.shared.b16 {%0,%1,%2,%3}, [%4];"
                 : "=r"(r[0]), "=r"(r[1]), "=r"(r[2]), "=r"(r[3]) : "r"(addr));
}
__device__ __forceinline__ void ldsm_x4_t(u32* r, u32 addr) {
    asm volatile("ldmatrix.sync.aligned.m8n8.x4.trans.shared.b16 {%0,%1,%2,%3}, [%4];"
                 : "=r"(r[0]), "=r"(r[1]), "=r"(r[2]), "=r"(r[3]) : "r"(addr));
}
__device__ __forceinline__ void mma_bf16(float* c, const u32* a, const u32* b) {
    asm volatile(
        "mma.sync.aligned.m16n8k16.row.col.f32.bf16.bf16.f32 "
        "{%0,%1,%2,%3}, {%4,%5,%6,%7}, {%8,%9}, {%0,%1,%2,%3};"
        : "+f"(c[0]), "+f"(c[1]), "+f"(c[2]), "+f"(c[3])
        : "r"(a[0]), "r"(a[1]), "r"(a[2]), "r"(a[3]), "r"(b[0]), "r"(b[1]));
}
__device__ __forceinline__ void cvt_hilo(float4 v, uint2& h, uint2& l) {
    __nv_bfloat162 h01 = __floats2bfloat162_rn(v.x, v.y);
    __nv_bfloat162 h23 = __floats2bfloat162_rn(v.z, v.w);
    __nv_bfloat162 l01 = __floats2bfloat162_rn(v.x - __bfloat162float(h01.x),
                                               v.y - __bfloat162float(h01.y));
    __nv_bfloat162 l23 = __floats2bfloat162_rn(v.z - __bfloat162float(h23.x),
                                               v.w - __bfloat162float(h23.y));
    h.x = *(u32*)&h01; h.y = *(u32*)&h23;
    l.x = *(u32*)&l01; l.y = *(u32*)&l23;
}

// ---------------------------------------------------------------------------
// Split-bf16 tensor GEMM: C[M,Nd] = A[M,Kd] @ W[Kd,Nd] (+bias)
// CTA 128 x BN, BK=16, 8 warps (4 m x 2 n), warp tile 32 x BN/2.
// fp32 emulated as Ah*Bh + Ah*Bl + Al*Bh (bf16 hi/lo split).
// qkv=1: grid.x = 3*(Nd/BN); t = bx>>3 selects {Wq,Wk,Wv}; scatter (B,H,S,HD).
// ---------------------------------------------------------------------------
template <int BN>
__global__ __launch_bounds__(256) void hmma_gemm(
    const float* __restrict__ Ain, int srcA,
    const float* __restrict__ W0, const float* __restrict__ W1,
    const float* __restrict__ W2,
    const float* __restrict__ b0p, const float* __restrict__ b1p,
    const float* __restrict__ b2p,
    float* __restrict__ Cout, int dstC, int Kd, int Nd, int qkv)
{
    constexpr int NF = BN / 16;              // 8-col frags per warp
    __shared__ __nv_bfloat16 Ah[2][128][24];
    __shared__ __nv_bfloat16 Al[2][128][24];
    __shared__ __nv_bfloat16 Bh[2][16][BN + 8];
    __shared__ __nv_bfloat16 Bl[2][16][BN + 8];

    const int tid  = threadIdx.x;
    const int wid  = tid >> 5, lane = tid & 31;
    const int wm   = wid & 3,  wn   = wid >> 2;
    const int m0   = wm * 32;
    const int bx = blockIdx.x, by = blockIdx.y;

    const float* A = (srcA >= 0) ? scratch_ptr(srcA) : Ain;
    const float* W;
    const float* bias;
    float* C;
    int n0glob;
    if (qkv) {
        int t = bx >> 3;
        n0glob = (bx & 7) * BN;
        W    = (t == 0) ? W0 : ((t == 1) ? W1 : W2);
        bias = (t == 0) ? b0p : ((t == 1) ? b1p : b2p);
        C    = (t == 0) ? g_Q : ((t == 1) ? g_K : g_V);
    } else {
        W = W0; bias = b0p; n0glob = bx * BN;
        C = (dstC >= 0) ? scratch_ptr(dstC) : Cout;
    }

    const float* Ab = A + (size_t)by * 128 * Kd;
    const int NC = Kd >> 4;

    // ldmatrix lane addressing
    const int g = lane >> 3, r = lane & 7;
    const int a_row = ((g & 1) << 3) + r;       // + m0 + mf*16
    const int a_col = (g >> 1) << 3;            // 0 or 8
    const int b_row = ((g & 1) << 3) + r;       // k row
    const int b_colg = (g >> 1) << 3;           // 0 or 8 within 16-col pair

    float acc[2][NF][4];
    #pragma unroll
    for (int mf = 0; mf < 2; mf++)
        #pragma unroll
        for (int nf = 0; nf < NF; nf++)
            #pragma unroll
            for (int i = 0; i < 4; i++) acc[mf][nf][i] = 0.f;

    constexpr int BTOT4 = 16 * BN / 4;          // float4s per B chunk
    constexpr int BPER  = (BTOT4 + 255) / 256;
    float4 sa[2], sb[BPER];

    // ---- prologue: load + store chunk 0 ----
    {
        #pragma unroll
        for (int p = 0; p < 2; p++) {
            int idx = tid + 256 * p;
            int row = idx >> 2, kq = (idx & 3) * 4;
            sa[p] = *(const float4*)(Ab + (size_t)row * Kd + kq);
        }
        #pragma unroll
        for (int p = 0; p < BPER; p++) {
            int idx = tid + 256 * p;
            if (idx < BTOT4) {
                int kr = idx / (BN / 4), nq = (idx % (BN / 4)) * 4;
                sb[p] = *(const float4*)(W + (size_t)kr * Nd + n0glob + nq);
            }
        }
        #pragma unroll
        for (int p = 0; p < 2; p++) {
            int idx = tid + 256 * p;
            int row = idx >> 2, kq = (idx & 3) * 4;
            uint2 h, l; cvt_hilo(sa[p], h, l);
            *(uint2*)&Ah[0][row][kq] = h;
            *(uint2*)&Al[0][row][kq] = l;
        }
        #pragma unroll
        for (int p = 0; p < BPER; p++) {
            int idx = tid + 256 * p;
            if (idx < BTOT4) {
                int kr = idx / (BN / 4), nq = (idx % (BN / 4)) * 4;
                uint2 h, l; cvt_hilo(sb[p], h, l);
                *(uint2*)&Bh[0][kr][nq] = h;
                *(uint2*)&Bl[0][kr][nq] = l;
            }
        }
    }
    __syncthreads();

    for (int c = 0; c < NC; c++) {
        const int buf = c & 1;
        const bool pre = (c + 1 < NC);

        // ---- issue next chunk's global loads ----
        if (pre) {
            const float* Ac = Ab + (c + 1) * 16;
            #pragma unroll
            for (int p = 0; p < 2; p++) {
                int idx = tid + 256 * p;
                int row = idx >> 2, kq = (idx & 3) * 4;
                sa[p] = *(const float4*)(Ac + (size_t)row * Kd + kq);
            }
            const float* Bc = W + (size_t)(c + 1) * 16 * Nd + n0glob;
            #pragma unroll
            for (int p = 0; p < BPER; p++) {
                int idx = tid + 256 * p;
                if (idx < BTOT4) {
                    int kr = idx / (BN / 4), nq = (idx % (BN / 4)) * 4;
                    sb[p] = *(const float4*)(Bc + (size_t)kr * Nd + nq);
                }
            }
        }

        // ---- compute on current buffer ----
        u32 afh[2][4], afl[2][4];
        #pragma unroll
        for (int mf = 0; mf < 2; mf++) {
            u32 ah = smem_u32(&Ah[buf][m0 + mf * 16 + a_row][a_col]);
            u32 al = smem_u32(&Al[buf][m0 + mf * 16 + a_row][a_col]);
            ldsm_x4(afh[mf], ah);
            ldsm_x4(afl[mf], al);
        }
        u32 bfh[NF][2], bfl[NF][2];
        #pragma unroll
        for (int nf2 = 0; nf2 < NF / 2; nf2++) {
            int bcol = wn * (BN / 2) + nf2 * 16 + b_colg;
            u32 t4[4];
            ldsm_x4_t(t4, smem_u32(&Bh[buf][b_row][bcol]));
            bfh[nf2 * 2][0] = t4[0]; bfh[nf2 * 2][1] = t4[1];
            bfh[nf2 * 2 + 1][0] = t4[2]; bfh[nf2 * 2 + 1][1] = t4[3];
            ldsm_x4_t(t4, smem_u32(&Bl[buf][b_row][bcol]));
            bfl[nf2 * 2][0] = t4[0]; bfl[nf2 * 2][1] = t4[1];
            bfl[nf2 * 2 + 1][0] = t4[2]; bfl[nf2 * 2 + 1][1] = t4[3];
        }
        #pragma unroll
        for (int mf = 0; mf < 2; mf++)
            #pragma unroll
            for (int nf = 0; nf < NF; nf++)
                mma_bf16(acc[mf][nf], afh[mf], bfh[nf]);
        #pragma unroll
        for (int mf = 0; mf < 2; mf++)
            #pragma unroll
            for (int nf = 0; nf < NF; nf++)
                mma_bf16(acc[mf][nf], afh[mf], bfl[nf]);
        #pragma unroll
        for (int mf = 0; mf < 2; mf++)
            #pragma unroll
            for (int nf = 0; nf < NF; nf++)
                mma_bf16(acc[mf][nf], afl[mf], bfh[nf]);

        // ---- store next chunk into other buffer ----
        if (pre) {
            #pragma unroll
            for (int p = 0; p < 2; p++) {
                int idx = tid + 256 * p;
                int row = idx >> 2, kq = (idx & 3) * 4;
                uint2 h, l; cvt_hilo(sa[p], h, l);
                *(uint2*)&Ah[buf ^ 1][row][kq] = h;
                *(uint2*)&Al[buf ^ 1][row][kq] = l;
            }
            #pragma unroll
            for (int p = 0; p < BPER; p++) {
                int idx = tid + 256 * p;
                if (idx < BTOT4) {
                    int kr = idx / (BN / 4), nq = (idx % (BN / 4)) * 4;
                    uint2 h, l; cvt_hilo(sb[p], h, l);
                    *(uint2*)&Bh[buf ^ 1][kr][nq] = h;
                    *(uint2*)&Bl[buf ^ 1][kr][nq] = l;
                }
            }
        }
        __syncthreads();
    }

    // ---- epilogue: direct stores ----
    #pragma unroll
    for (int mf = 0; mf < 2; mf++) {
        #pragma unroll
        for (int nf = 0; nf < NF; nf++) {
            int mrow = by * 128 + m0 + mf * 16 + (lane >> 2);
            int ncol = n0glob + wn * (BN / 2) + nf * 8 + (lane & 3) * 2;
            float bv0 = bias ? bias[ncol] : 0.f;
            float bv1 = bias ? bias[ncol + 1] : 0.f;
            #pragma unroll
            for (int half = 0; half < 2; half++) {
                int mr = mrow + half * 8;
                float v0 = acc[mf][nf][half * 2 + 0] + bv0;
                float v1 = acc[mf][nf][half * 2 + 1] + bv1;
                float* p;
                if (qkv) {
                    int bb = mr >> 6, ss = mr & 63;
                    int h = ncol >> 6, d = ncol & 63;
                    p = C + ((((size_t)bb * NH + h) * SEQ + ss) * HD) + d;
                } else {
                    p = C + (size_t)mr * Nd + ncol;
                }
                p[0] = v0; p[1] = v1;
            }
        }
    }
}

// ---------------------------------------------------------------------------
// silu + LayerNorm over last dim: out = LN(silu(in)) * g + be
// ---------------------------------------------------------------------------
__global__ __launch_bounds__(256) void silu_ln_kernel(
    const float* __restrict__ g, const float* __restrict__ be,
    int N, int srcIdx, int dstIdx)
{
    const float* in = scratch_ptr(srcIdx);
    float* out = scratch_ptr(dstIdx);

    __shared__ float hs[4096];
    __shared__ float red[2][8];

    const int row = blockIdx.x;
    const int tid = threadIdx.x;
    const float* pin = in + (size_t)row * N;

    float sum = 0.f, sq = 0.f;
    for (int i = tid; i < N; i += 256) {
        float y = pin[i];
        float h = y / (1.f + expf(-y));
        hs[i] = h;
        sum += h;
        sq  += h * h;
    }
    #pragma unroll
    for (int off = 16; off > 0; off >>= 1) {
        sum += __shfl_xor_sync(0xffffffffu, sum, off);
        sq  += __shfl_xor_sync(0xffffffffu, sq,  off);
    }
    if ((tid & 31) == 0) { red[0][tid >> 5] = sum; red[1][tid >> 5] = sq; }
    __syncthreads();
    if (tid < 32) {
        float s = (tid < 8) ? red[0][tid] : 0.f;
        float q = (tid < 8) ? red[1][tid] : 0.f;
        #pragma unroll
        for (int off = 4; off > 0; off >>= 1) {
            s += __shfl_xor_sync(0xffffffffu, s, off);
            q += __shfl_xor_sync(0xffffffffu, q, off);
        }
        if (tid == 0) { red[0][0] = s; red[1][0] = q; }
    }
    __syncthreads();
    const float mean = red[0][0] / (float)N;
    const float var  = red[1][0] / (float)N - mean * mean;
    const float inv  = rsqrtf(var + LN_EPS);

    for (int i = tid; i < N; i += 256)
        out[(size_t)row * N + i] = (hs[i] - mean) * inv * g[i] + be[i];
}

// ---------------------------------------------------------------------------
// Attention: per (b,h): softmax(q@k^T*scale + bias) @ v -> g_ATT (B,S,E)
// ---------------------------------------------------------------------------
__global__ __launch_bounds__(256) void attn_kernel()
{
    __shared__ float ks[64][65];
    __shared__ float vs[64][65];
    __shared__ float ps[8][64];

    const int bh = blockIdx.x;
    const int b = bh >> 4, h = bh & 15;
    const int tid = threadIdx.x;
    const float* kp = g_K + (size_t)bh * (SEQ * HD);
    const float* vp = g_V + (size_t)bh * (SEQ * HD);
    const float* qp = g_Q + (size_t)bh * (SEQ * HD);
    const float* bp = g_BIAS + (size_t)bh * (SEQ * SEQ);

    #pragma unroll
    for (int p = 0; p < 4; p++) {
        int idx = tid + 256 * p;
        int s = idx >> 4, d4 = (idx & 15) * 4;
        float4 kv = *(const float4*)(kp + s * HD + d4);
        ks[s][d4] = kv.x; ks[s][d4 + 1] = kv.y; ks[s][d4 + 2] = kv.z; ks[s][d4 + 3] = kv.w;
        float4 vv = *(const float4*)(vp + s * HD + d4);
        vs[s][d4] = vv.x; vs[s][d4 + 1] = vv.y; vs[s][d4 + 2] = vv.z; vs[s][d4 + 3] = vv.w;
    }
    __syncthreads();

    const int w = tid >> 5, lane = tid & 31;
    const float scale = 0.125f;

    for (int r = w * 8; r < w * 8 + 8; r++) {
        const float* q = qp + r * HD;
        float dot0 = 0.f, dot1 = 0.f;
        #pragma unroll
        for (int k = 0; k < 64; k++) {
            float qk = __ldg(q + k);
            dot0 += qk * ks[lane][k];
            dot1 += qk * ks[lane + 32][k];
        }
        float acc0 = dot0 * scale + bp[r * 64 + lane];
        float acc1 = dot1 * scale + bp[r * 64 + lane + 32];

        float m = fmaxf(acc0, acc1);
        #pragma unroll
        for (int off = 16; off > 0; off >>= 1)
            m = fmaxf(m, __shfl_xor_sync(0xffffffffu, m, off));
        float e0 = __expf(acc0 - m), e1 = __expf(acc1 - m);
        float s = e0 + e1;
        #pragma unroll
        for (int off = 16; off > 0; off >>= 1)
            s += __shfl_xor_sync(0xffffffffu, s, off);
        float invs = 1.f / s;

        __syncwarp();
        ps[w][lane]      = e0 * invs;
        ps[w][lane + 32] = e1 * invs;
        __syncwarp();

        float o0 = 0.f, o1 = 0.f;
        #pragma unroll
        for (int j = 0; j < 64; j++) {
            float pj = ps[w][j];
            o0 += pj * vs[j][lane];
            o1 += pj * vs[j][lane + 32];
        }
        float* op = g_ATT + ((size_t)(b * SEQ + r) * EMB) + h * HD;
        op[lane]      = o0;
        op[lane + 32] = o1;
    }
}

// ---------------------------------------------------------------------------
// kernel_launch
// ---------------------------------------------------------------------------
extern "C" void kernel_launch(void* const* d_in, const int* in_sizes, int n_in,
                              void* d_out, int out_size)
{
    const float* x   = (const float*)d_in[0];
    const float* Wq  = (const float*)d_in[1];
    const float* bq  = (const float*)d_in[2];
    const float* Wk  = (const float*)d_in[3];
    const float* bk  = (const float*)d_in[4];
    const float* Wv  = (const float*)d_in[5];
    const float* bv  = (const float*)d_in[6];
    const float* Wo  = (const float*)d_in[7];
    const float* bo  = (const float*)d_in[8];
    const float* Wc  = (const float*)d_in[9];
    const float* Wd1 = (const float*)d_in[10];
    const float* bd1 = (const float*)d_in[11];
    const float* g1  = (const float*)d_in[12];
    const float* be1 = (const float*)d_in[13];
    const float* Wd2 = (const float*)d_in[14];
    const float* bd2 = (const float*)d_in[15];
    const float* g2  = (const float*)d_in[16];
    const float* be2 = (const float*)d_in[17];
    const float* Wg  = (const float*)d_in[18];

    // ---- Fused QKV: (65536,1024)@(1024,1024) x3, scatter to (B,H,S,HD) ----
    hmma_gemm<128><<<dim3(24, 512), 256>>>(
        x, -1, Wq, Wk, Wv, bq, bk, bv, nullptr, -2, EMB, EMB, 1);

    // ---- Smolgen compress: (65536,1024)@(1024,32) -> g_COMP ----
    hmma_gemm<32><<<dim3(1, 512), 256>>>(
        x, -1, Wc, nullptr, nullptr, nullptr, nullptr, nullptr,
        nullptr, 3, EMB, HC, 0);

    // ---- dense1: (1024,2048)@(2048,256) + bd1 -> g_T1 ----
    hmma_gemm<128><<<dim3(2, 8), 256>>>(
        nullptr, 3, Wd1, nullptr, nullptr, bd1, nullptr, nullptr,
        nullptr, 4, SEQ * HC, HS, 0);
    silu_ln_kernel<<<BATCH, 256>>>(g1, be1, HS, 4, 5);

    // ---- dense2: (1024,256)@(256,4096) + bd2 -> g_T2 ----
    hmma_gemm<128><<<dim3(32, 8), 256>>>(
        nullptr, 5, Wd2, nullptr, nullptr, bd2, nullptr, nullptr,
        nullptr, 6, HS, GS * NH, 0);
    silu_ln_kernel<<<BATCH, 256>>>(g2, be2, GS * NH, 6, 7);

    // ---- bias-gen: (16384,256)@(256,4096) -> g_BIAS ----
    hmma_gemm<128><<<dim3(32, 128), 256>>>(
        nullptr, 7, Wg, nullptr, nullptr, nullptr, nullptr, nullptr,
        nullptr, 8, GS, SEQ * SEQ, 0);

    // ---- Attention ----
    attn_kernel<<<BATCH * NH, 256>>>();

    // ---- Output projection: (65536,1024)@(1024,1024) + bo -> d_out ----
    hmma_gemm<128><<<dim3(8, 512), 256>>>(
        nullptr, 9, Wo, nullptr, nullptr, bo, nullptr, nullptr,
        (float*)d_out, -1, EMB, EMB, 0);
}

// round 7
// speedup vs baseline: 2.1743x; 1.3083x over previous
#include <cuda_runtime.h>
#include <cuda_bf16.h>
#include <math.h>

typedef unsigned int u32;
typedef __nv_bfloat16 bf16;

// ---------------------------------------------------------------------------
// Problem constants
// ---------------------------------------------------------------------------
#define BATCH 1024
#define SEQ   64
#define EMB   1024
#define NH    16
#define HD    64
#define HC    32
#define HS    256
#define GS    256
#define LN_EPS 1e-3f

// ---------------------------------------------------------------------------
// fp32 scratch
// ---------------------------------------------------------------------------
__device__ float g_Q   [BATCH * NH * SEQ * HD];
__device__ float g_K   [BATCH * NH * SEQ * HD];
__device__ float g_V   [BATCH * NH * SEQ * HD];
__device__ float g_T1  [BATCH * HS];
__device__ float g_T2  [BATCH * GS * NH];
__device__ float g_BIAS[BATCH * NH * SEQ * SEQ];

__device__ __forceinline__ float* scratch_ptr(int which) {
    switch (which) {
        case 0: return g_Q;  case 1: return g_K;  case 2: return g_V;
        case 3: return g_T1; case 4: return g_T2; default: return g_BIAS;
    }
}

// ---------------------------------------------------------------------------
// bf16 hi/lo pairs (split fp32 emulation operands)
// ---------------------------------------------------------------------------
#define NX (BATCH * SEQ * EMB)
__device__ __align__(16) bf16 g_Xh[NX],   g_Xl[NX];
__device__ __align__(16) bf16 g_ATTh[NX], g_ATTl[NX];
__device__ __align__(16) bf16 g_COMPh[BATCH * SEQ * HC], g_COMPl[BATCH * SEQ * HC];
__device__ __align__(16) bf16 g_HIDh[BATCH * HS],        g_HIDl[BATCH * HS];
__device__ __align__(16) bf16 g_GENh[BATCH * GS * NH],   g_GENl[BATCH * GS * NH];
__device__ __align__(16) bf16 g_Wqh[EMB * EMB],  g_Wql[EMB * EMB];
__device__ __align__(16) bf16 g_Wkh[EMB * EMB],  g_Wkl[EMB * EMB];
__device__ __align__(16) bf16 g_Wvh[EMB * EMB],  g_Wvl[EMB * EMB];
__device__ __align__(16) bf16 g_Woh[EMB * EMB],  g_Wol[EMB * EMB];
__device__ __align__(16) bf16 g_Wgh[GS * SEQ * SEQ], g_Wgl[GS * SEQ * SEQ];
__device__ __align__(16) bf16 g_Wd1h[SEQ * HC * HS], g_Wd1l[SEQ * HC * HS];
__device__ __align__(16) bf16 g_Wd2h[HS * GS * NH],  g_Wd2l[HS * GS * NH];
__device__ __align__(16) bf16 g_Wch[EMB * HC],       g_Wcl[EMB * HC];

__device__ __forceinline__ bf16* pairH(int i) {
    switch (i) {
        case 0: return g_Xh;   case 1: return g_ATTh; case 2: return g_COMPh;
        case 3: return g_HIDh; case 4: return g_GENh; case 5: return g_Wqh;
        case 6: return g_Wkh;  case 7: return g_Wvh;  case 8: return g_Woh;
        case 9: return g_Wgh;  case 10: return g_Wd1h; case 11: return g_Wd2h;
        default: return g_Wch;
    }
}
__device__ __forceinline__ bf16* pairL(int i) {
    switch (i) {
        case 0: return g_Xl;   case 1: return g_ATTl; case 2: return g_COMPl;
        case 3: return g_HIDl; case 4: return g_GENl; case 5: return g_Wql;
        case 6: return g_Wkl;  case 7: return g_Wvl;  case 8: return g_Wol;
        case 9: return g_Wgl;  case 10: return g_Wd1l; case 11: return g_Wd2l;
        default: return g_Wcl;
    }
}

// ---------------------------------------------------------------------------
// PTX helpers
// ---------------------------------------------------------------------------
__device__ __forceinline__ u32 smem_u32(const void* p) {
    u32 a;
    asm("{ .reg .u64 t; cvta.to.shared.u64 t, %1; cvt.u32.u64 %0, t; }" : "=r"(a) : "l"(p));
    return a;
}
__device__ __forceinline__ void ldsm_x4(u32* r, u32 addr) {
    asm volatile("ldmatrix.sync.aligned.m8n8.x4.shared.b16 {%0,%1,%2,%3}, [%4];"
                 : "=r"(r[0]), "=r"(r[1]), "=r"(r[2]), "=r"(r[3]) : "r"(addr));
}
__device__ __forceinline__ void ldsm_x4_t(u32* r, u32 addr) {
    asm volatile("ldmatrix.sync.aligned.m8n8.x4.trans.shared.b16 {%0,%1,%2,%3}, [%4];"
                 : "=r"(r[0]), "=r"(r[1]), "=r"(r[2]), "=r"(r[3]) : "r"(addr));
}
__device__ __forceinline__ void mma_bf16(float* c, const u32* a, const u32* b) {
    asm volatile(
        "mma.sync.aligned.m16n8k16.row.col.f32.bf16.bf16.f32 "
        "{%0,%1,%2,%3}, {%4,%5,%6,%7}, {%8,%9}, {%0,%1,%2,%3};"
        : "+f"(c[0]), "+f"(c[1]), "+f"(c[2]), "+f"(c[3])
        : "r"(a[0]), "r"(a[1]), "r"(a[2]), "r"(a[3]), "r"(b[0]), "r"(b[1]));
}
#define CP_ASYNC16(dst, src) \
    asm volatile("cp.async.cg.shared.global [%0], [%1], 16;" :: "r"(dst), "l"(src))
#define CP_COMMIT() asm volatile("cp.async.commit_group;" ::: "memory")
#define CP_WAIT3()  asm volatile("cp.async.wait_group 3;" ::: "memory")

__device__ __forceinline__ void split2(float v0, float v1, __nv_bfloat162& h, __nv_bfloat162& l) {
    h = __floats2bfloat162_rn(v0, v1);
    l = __floats2bfloat162_rn(v0 - __bfloat162float(h.x), v1 - __bfloat162float(h.y));
}

// ---------------------------------------------------------------------------
// prep_split: fp32 -> bf16 hi/lo pair (count % 4 == 0)
// ---------------------------------------------------------------------------
__global__ __launch_bounds__(256) void prep_split(
    const float* __restrict__ src, int pIdx, int count)
{
    bf16* H = pairH(pIdx);
    bf16* L = pairL(pIdx);
    int n4 = count >> 2;
    for (int i = blockIdx.x * 256 + threadIdx.x; i < n4; i += gridDim.x * 256) {
        float4 v = *(const float4*)(src + (size_t)i * 4);
        __nv_bfloat162 h01, l01, h23, l23;
        split2(v.x, v.y, h01, l01);
        split2(v.z, v.w, h23, l23);
        uint2 hv, lv;
        hv.x = *(u32*)&h01; hv.y = *(u32*)&h23;
        lv.x = *(u32*)&l01; lv.y = *(u32*)&l23;
        *(uint2*)(H + (size_t)i * 4) = hv;
        *(uint2*)(L + (size_t)i * 4) = lv;
    }
}

// ---------------------------------------------------------------------------
// Split-bf16 HMMA GEMM, cp.async 4-stage pipeline, BK=16, CTA 128 x BN.
// A from pair aSel (row-major M x Kd), B from pair bSel (row-major Kd x Nd).
// mode 0: fp32 C row-major (+bias). mode 1: QKV fp32 scatter. mode 2: bf16
// hi/lo pair outSel row-major (+bias).
// qkv=1: grid.x = 3*(Nd/BN); t = bx>>3 selects B pair 5+t / bias / Q,K,V.
// ---------------------------------------------------------------------------
template <int BN>
__global__ __launch_bounds__(256, 2) void hmma_gemm(
    int aSel, int bSel,
    const float* __restrict__ b0p, const float* __restrict__ b1p,
    const float* __restrict__ b2p,
    float* __restrict__ Cout, int dstC, int outSel,
    int Kd, int Nd, int mode)
{
    constexpr int NF    = BN / 16;
    constexpr int SEGS  = BN / 8;
    constexpr int BSTR  = BN + 8;
    constexpr int AELEM = 128 * 24;          // one matrix (hi or lo)
    constexpr int BELEM = 16 * BSTR;
    constexpr int STAGE = 2 * AELEM + 2 * BELEM;
    constexpr int NB    = 2 * 16 * SEGS;     // B cp.asyncs per stage
    constexpr int NTOT  = 512 + NB;

    extern __shared__ __align__(16) bf16 smp[];

    const int tid = threadIdx.x;
    const int wid = tid >> 5, lane = tid & 31;
    const int wm = wid & 3, wn = wid >> 2;
    const int m0 = wm * 32;
    const int bx = blockIdx.x, by = blockIdx.y;

    const bf16* Agh = pairH(aSel);
    const bf16* Agl = pairL(aSel);
    const bf16 *Bgh, *Bgl;
    const float* bias;
    float* C = nullptr;
    int n0glob;
    if (mode == 1) {
        int t = bx >> 3;
        n0glob = (bx & 7) * BN;
        Bgh = pairH(5 + t); Bgl = pairL(5 + t);
        bias = (t == 0) ? b0p : ((t == 1) ? b1p : b2p);
        C    = (t == 0) ? g_Q : ((t == 1) ? g_K : g_V);
    } else {
        Bgh = pairH(bSel); Bgl = pairL(bSel);
        bias = b0p; n0glob = bx * BN;
        if (mode == 0) C = (dstC >= 0) ? scratch_ptr(dstC) : Cout;
    }

    const size_t aBase = (size_t)by * 128 * Kd;
    const int NC = Kd >> 4;

    // ldmatrix lane addressing
    const int g = lane >> 3, r = lane & 7;
    const int a_row = ((g & 1) << 3) + r;
    const int a_col = (g >> 1) << 3;
    const int b_row = ((g & 1) << 3) + r;
    const int b_colg = (g >> 1) << 3;

    float acc[2][NF][4];
    #pragma unroll
    for (int mf = 0; mf < 2; mf++)
        #pragma unroll
        for (int nf = 0; nf < NF; nf++)
            #pragma unroll
            for (int i = 0; i < 4; i++) acc[mf][nf][i] = 0.f;

    // cp.async issue for one chunk into stage s
    auto issue = [&](int c, int s) {
        bf16* st = smp + s * STAGE;
        const int k0 = c << 4;
        #pragma unroll 4
        for (int i = tid; i < NTOT; i += 256) {
            if (i < 512) {
                int mat = i >> 8;             // 0=hi 1=lo
                int rem = i & 255;
                int row = rem >> 1, half = rem & 1;
                const bf16* src = (mat ? Agl : Agh) + aBase + (size_t)row * Kd + k0 + half * 8;
                bf16* dst = st + mat * AELEM + row * 24 + half * 8;
                CP_ASYNC16(smem_u32(dst), src);
            } else {
                int j = i - 512;
                int mat = j / (16 * SEGS);
                int rem = j % (16 * SEGS);
                int row = rem / SEGS, seg = rem % SEGS;
                const bf16* src = (mat ? Bgl : Bgh) + (size_t)(k0 + row) * Nd + n0glob + seg * 8;
                bf16* dst = st + 2 * AELEM + mat * BELEM + row * BSTR + seg * 8;
                CP_ASYNC16(smem_u32(dst), src);
            }
        }
    };

    // prologue: stages 0..2
    for (int s = 0; s < 3; s++) {
        if (s < NC) issue(s, s);
        CP_COMMIT();
    }

    for (int c = 0; c < NC; c++) {
        if (c + 3 < NC) issue(c + 3, (c + 3) & 3);
        CP_COMMIT();
        CP_WAIT3();
        __syncthreads();

        bf16* st = smp + (c & 3) * STAGE;
        bf16* sAh = st;
        bf16* sAl = st + AELEM;
        bf16* sBh = st + 2 * AELEM;
        bf16* sBl = sBh + BELEM;

        u32 afh[2][4], afl[2][4];
        #pragma unroll
        for (int mf = 0; mf < 2; mf++) {
            ldsm_x4(afh[mf], smem_u32(sAh + (m0 + mf * 16 + a_row) * 24 + a_col));
            ldsm_x4(afl[mf], smem_u32(sAl + (m0 + mf * 16 + a_row) * 24 + a_col));
        }
        #pragma unroll
        for (int nf2 = 0; nf2 < NF / 2; nf2++) {
            int bcol = wn * (BN / 2) + nf2 * 16 + b_colg;
            u32 bh4[4], bl4[4];
            ldsm_x4_t(bh4, smem_u32(sBh + b_row * BSTR + bcol));
            ldsm_x4_t(bl4, smem_u32(sBl + b_row * BSTR + bcol));
            #pragma unroll
            for (int mf = 0; mf < 2; mf++) {
                mma_bf16(acc[mf][nf2 * 2 + 0], afh[mf], bh4 + 0);
                mma_bf16(acc[mf][nf2 * 2 + 1], afh[mf], bh4 + 2);
                mma_bf16(acc[mf][nf2 * 2 + 0], afh[mf], bl4 + 0);
                mma_bf16(acc[mf][nf2 * 2 + 1], afh[mf], bl4 + 2);
                mma_bf16(acc[mf][nf2 * 2 + 0], afl[mf], bh4 + 0);
                mma_bf16(acc[mf][nf2 * 2 + 1], afl[mf], bh4 + 2);
            }
        }
        __syncthreads();
    }

    // ---- epilogue ----
    #pragma unroll
    for (int mf = 0; mf < 2; mf++) {
        #pragma unroll
        for (int nf = 0; nf < NF; nf++) {
            int mrow = by * 128 + m0 + mf * 16 + (lane >> 2);
            int ncol = n0glob + wn * (BN / 2) + nf * 8 + (lane & 3) * 2;
            float bv0 = bias ? bias[ncol] : 0.f;
            float bv1 = bias ? bias[ncol + 1] : 0.f;
            #pragma unroll
            for (int half = 0; half < 2; half++) {
                int mr = mrow + half * 8;
                float v0 = acc[mf][nf][half * 2 + 0] + bv0;
                float v1 = acc[mf][nf][half * 2 + 1] + bv1;
                if (mode == 1) {
                    int bb = mr >> 6, ss = mr & 63;
                    int h = ncol >> 6, d = ncol & 63;
                    float* p = C + ((((size_t)bb * NH + h) * SEQ + ss) * HD) + d;
                    p[0] = v0; p[1] = v1;
                } else if (mode == 0) {
                    float* p = C + (size_t)mr * Nd + ncol;
                    p[0] = v0; p[1] = v1;
                } else {
                    __nv_bfloat162 h2, l2;
                    split2(v0, v1, h2, l2);
                    *(__nv_bfloat162*)(pairH(outSel) + (size_t)mr * Nd + ncol) = h2;
                    *(__nv_bfloat162*)(pairL(outSel) + (size_t)mr * Nd + ncol) = l2;
                }
            }
        }
    }
}

// ---------------------------------------------------------------------------
// silu + LN: out pair = LN(silu(in)) * g + be   (fp32 in scratch, bf16 out)
// ---------------------------------------------------------------------------
__global__ __launch_bounds__(256) void silu_ln_kernel(
    const float* __restrict__ g, const float* __restrict__ be,
    int N, int srcIdx, int outPair)
{
    const float* in = scratch_ptr(srcIdx);
    bf16* H = pairH(outPair);
    bf16* L = pairL(outPair);

    __shared__ float hs[4096];
    __shared__ float red[2][8];

    const int row = blockIdx.x;
    const int tid = threadIdx.x;
    const float* pin = in + (size_t)row * N;

    float sum = 0.f, sq = 0.f;
    for (int i = tid; i < N; i += 256) {
        float y = pin[i];
        float h = y / (1.f + expf(-y));
        hs[i] = h;
        sum += h;
        sq  += h * h;
    }
    #pragma unroll
    for (int off = 16; off > 0; off >>= 1) {
        sum += __shfl_xor_sync(0xffffffffu, sum, off);
        sq  += __shfl_xor_sync(0xffffffffu, sq,  off);
    }
    if ((tid & 31) == 0) { red[0][tid >> 5] = sum; red[1][tid >> 5] = sq; }
    __syncthreads();
    if (tid < 32) {
        float s = (tid < 8) ? red[0][tid] : 0.f;
        float q = (tid < 8) ? red[1][tid] : 0.f;
        #pragma unroll
        for (int off = 4; off > 0; off >>= 1) {
            s += __shfl_xor_sync(0xffffffffu, s, off);
            q += __shfl_xor_sync(0xffffffffu, q, off);
        }
        if (tid == 0) { red[0][0] = s; red[1][0] = q; }
    }
    __syncthreads();
    const float mean = red[0][0] / (float)N;
    const float var  = red[1][0] / (float)N - mean * mean;
    const float inv  = rsqrtf(var + LN_EPS);

    for (int i = tid * 2; i < N; i += 512) {
        float v0 = (hs[i] - mean) * inv * g[i] + be[i];
        float v1 = (hs[i + 1] - mean) * inv * g[i + 1] + be[i + 1];
        __nv_bfloat162 h2, l2;
        split2(v0, v1, h2, l2);
        *(__nv_bfloat162*)(H + (size_t)row * N + i) = h2;
        *(__nv_bfloat162*)(L + (size_t)row * N + i) = l2;
    }
}

// ---------------------------------------------------------------------------
// Attention: softmax(q@k^T*scale + bias) @ v -> ATT pair (B,S,E as hi/lo bf16)
// ---------------------------------------------------------------------------
__global__ __launch_bounds__(256) void attn_kernel()
{
    __shared__ float ks[64][65];
    __shared__ float vs[64][65];
    __shared__ float ps[8][64];

    const int bh = blockIdx.x;
    const int b = bh >> 4, h = bh & 15;
    const int tid = threadIdx.x;
    const float* kp = g_K + (size_t)bh * (SEQ * HD);
    const float* vp = g_V + (size_t)bh * (SEQ * HD);
    const float* qp = g_Q + (size_t)bh * (SEQ * HD);
    const float* bp = g_BIAS + (size_t)bh * (SEQ * SEQ);

    #pragma unroll
    for (int p = 0; p < 4; p++) {
        int idx = tid + 256 * p;
        int s = idx >> 4, d4 = (idx & 15) * 4;
        float4 kv = *(const float4*)(kp + s * HD + d4);
        ks[s][d4] = kv.x; ks[s][d4 + 1] = kv.y; ks[s][d4 + 2] = kv.z; ks[s][d4 + 3] = kv.w;
        float4 vv = *(const float4*)(vp + s * HD + d4);
        vs[s][d4] = vv.x; vs[s][d4 + 1] = vv.y; vs[s][d4 + 2] = vv.z; vs[s][d4 + 3] = vv.w;
    }
    __syncthreads();

    const int w = tid >> 5, lane = tid & 31;
    const float scale = 0.125f;

    for (int r = w * 8; r < w * 8 + 8; r++) {
        const float* q = qp + r * HD;
        float dot0 = 0.f, dot1 = 0.f;
        #pragma unroll
        for (int k = 0; k < 64; k++) {
            float qk = __ldg(q + k);
            dot0 += qk * ks[lane][k];
            dot1 += qk * ks[lane + 32][k];
        }
        float acc0 = dot0 * scale + bp[r * 64 + lane];
        float acc1 = dot1 * scale + bp[r * 64 + lane + 32];

        float m = fmaxf(acc0, acc1);
        #pragma unroll
        for (int off = 16; off > 0; off >>= 1)
            m = fmaxf(m, __shfl_xor_sync(0xffffffffu, m, off));
        float e0 = __expf(acc0 - m), e1 = __expf(acc1 - m);
        float s = e0 + e1;
        #pragma unroll
        for (int off = 16; off > 0; off >>= 1)
            s += __shfl_xor_sync(0xffffffffu, s, off);
        float invs = 1.f / s;

        __syncwarp();
        ps[w][lane]      = e0 * invs;
        ps[w][lane + 32] = e1 * invs;
        __syncwarp();

        float o0 = 0.f, o1 = 0.f;
        #pragma unroll
        for (int j = 0; j < 64; j++) {
            float pj = ps[w][j];
            o0 += pj * vs[j][lane];
            o1 += pj * vs[j][lane + 32];
        }
        size_t off0 = ((size_t)(b * SEQ + r) * EMB) + h * HD + lane;
        bf16 h0 = __float2bfloat16(o0);
        bf16 h1 = __float2bfloat16(o1);
        g_ATTh[off0]      = h0;
        g_ATTh[off0 + 32] = h1;
        g_ATTl[off0]      = __float2bfloat16(o0 - __bfloat162float(h0));
        g_ATTl[off0 + 32] = __float2bfloat16(o1 - __bfloat162float(h1));
    }
}

// ---------------------------------------------------------------------------
// kernel_launch
// ---------------------------------------------------------------------------
extern "C" void kernel_launch(void* const* d_in, const int* in_sizes, int n_in,
                              void* d_out, int out_size)
{
    const float* x   = (const float*)d_in[0];
    const float* Wq  = (const float*)d_in[1];
    const float* bq  = (const float*)d_in[2];
    const float* Wk  = (const float*)d_in[3];
    const float* bk  = (const float*)d_in[4];
    const float* Wv  = (const float*)d_in[5];
    const float* bv  = (const float*)d_in[6];
    const float* Wo  = (const float*)d_in[7];
    const float* bo  = (const float*)d_in[8];
    const float* Wc  = (const float*)d_in[9];
    const float* Wd1 = (const float*)d_in[10];
    const float* bd1 = (const float*)d_in[11];
    const float* g1  = (const float*)d_in[12];
    const float* be1 = (const float*)d_in[13];
    const float* Wd2 = (const float*)d_in[14];
    const float* bd2 = (const float*)d_in[15];
    const float* g2  = (const float*)d_in[16];
    const float* be2 = (const float*)d_in[17];
    const float* Wg  = (const float*)d_in[18];

    // dynamic smem sizes
    const int smem128 = 4 * (2 * 128 * 24 + 2 * 16 * (128 + 8)) * (int)sizeof(bf16);
    const int smem32  = 4 * (2 * 128 * 24 + 2 * 16 * (32 + 8))  * (int)sizeof(bf16);
    cudaFuncSetAttribute(hmma_gemm<128>, cudaFuncAttributeMaxDynamicSharedMemorySize, smem128);
    cudaFuncSetAttribute(hmma_gemm<32>,  cudaFuncAttributeMaxDynamicSharedMemorySize, smem32);

    // ---- split inputs/weights to bf16 hi/lo ----
    prep_split<<<4096, 256>>>(x,   0, NX);
    prep_split<<<256, 256>>>(Wq,  5, EMB * EMB);
    prep_split<<<256, 256>>>(Wk,  6, EMB * EMB);
    prep_split<<<256, 256>>>(Wv,  7, EMB * EMB);
    prep_split<<<256, 256>>>(Wo,  8, EMB * EMB);
    prep_split<<<256, 256>>>(Wg,  9, GS * SEQ * SEQ);
    prep_split<<<128, 256>>>(Wd1, 10, SEQ * HC * HS);
    prep_split<<<256, 256>>>(Wd2, 11, HS * GS * NH);
    prep_split<<<32,  256>>>(Wc,  12, EMB * HC);

    // ---- Fused QKV (mode 1) ----
    hmma_gemm<128><<<dim3(24, 512), 256, smem128>>>(
        0, -1, bq, bk, bv, nullptr, -1, -1, EMB, EMB, 1);

    // ---- compress -> COMP pair (mode 2) ----
    hmma_gemm<32><<<dim3(1, 512), 256, smem32>>>(
        0, 12, nullptr, nullptr, nullptr, nullptr, -1, 2, EMB, HC, 2);

    // ---- dense1 -> T1 fp32 ----
    hmma_gemm<128><<<dim3(2, 8), 256, smem128>>>(
        2, 10, bd1, nullptr, nullptr, nullptr, 3, -1, SEQ * HC, HS, 0);
    silu_ln_kernel<<<BATCH, 256>>>(g1, be1, HS, 3, 3);

    // ---- dense2 -> T2 fp32 ----
    hmma_gemm<128><<<dim3(32, 8), 256, smem128>>>(
        3, 11, bd2, nullptr, nullptr, nullptr, 4, -1, HS, GS * NH, 0);
    silu_ln_kernel<<<BATCH, 256>>>(g2, be2, GS * NH, 4, 4);

    // ---- bias-gen -> BIAS fp32 ----
    hmma_gemm<128><<<dim3(32, 128), 256, smem128>>>(
        4, 9, nullptr, nullptr, nullptr, nullptr, 5, -1, GS, SEQ * SEQ, 0);

    // ---- attention -> ATT pair ----
    attn_kernel<<<BATCH * NH, 256>>>();

    // ---- output projection -> d_out ----
    hmma_gemm<128><<<dim3(8, 512), 256, smem128>>>(
        1, 8, bo, nullptr, nullptr, (float*)d_out, -1, -1, EMB, EMB, 0);
}

// round 8
// speedup vs baseline: 2.6298x; 1.2095x over previous
#include <cuda_runtime.h>
#include <cuda_bf16.h>
#include <math.h>

typedef unsigned int u32;
typedef unsigned long long u64;
typedef __nv_bfloat16 bf16;

// ---------------------------------------------------------------------------
// Problem constants
// ---------------------------------------------------------------------------
#define BATCH 1024
#define SEQ   64
#define EMB   1024
#define NH    16
#define HD    64
#define HC    32
#define HS    256
#define GS    256
#define LN_EPS 1e-3f

// ---------------------------------------------------------------------------
// fp32 scratch
// ---------------------------------------------------------------------------
__device__ float g_Q   [BATCH * NH * SEQ * HD];
__device__ float g_K   [BATCH * NH * SEQ * HD];
__device__ float g_V   [BATCH * NH * SEQ * HD];
__device__ float g_T1  [BATCH * HS];
__device__ float g_T2  [BATCH * GS * NH];
__device__ float g_BIAS[BATCH * NH * SEQ * SEQ];
__device__ float g_ATT [BATCH * SEQ * EMB];

__device__ __forceinline__ float* scratch_ptr(int which) {
    switch (which) {
        case 0: return g_Q;  case 1: return g_K;   case 2: return g_V;
        case 3: return g_T1; case 4: return g_T2;  case 5: return g_BIAS;
        default: return g_ATT;
    }
}

// ---------------------------------------------------------------------------
// Packed tile images: [rowBlk/ntile][chunk] of 8192B = [hi 4KB | lo 4KB]
// A tile: 128 rows x 16 k (row r at r*32, halves swizzled: half ^= (r>>2)&1)
// B tile: 16 k x 128 n (row k at k*256, granule g at ((g + k)&15)*16)
// ---------------------------------------------------------------------------
__device__ __align__(16) bf16 g_Xp   [512 * 64 * 4096];   // X: M=65536, K=1024
__device__ __align__(16) bf16 g_ATTp [512 * 64 * 4096];
__device__ __align__(16) bf16 g_COMPp[8 * 128 * 4096];    // M=1024, K=2048
__device__ __align__(16) bf16 g_HIDp [8 * 16 * 4096];     // M=1024, K=256
__device__ __align__(16) bf16 g_GENp [128 * 16 * 4096];   // M=16384, K=256
__device__ __align__(16) bf16 g_WqP  [8 * 64 * 4096];
__device__ __align__(16) bf16 g_WkP  [8 * 64 * 4096];
__device__ __align__(16) bf16 g_WvP  [8 * 64 * 4096];
__device__ __align__(16) bf16 g_WoP  [8 * 64 * 4096];
__device__ __align__(16) bf16 g_WgP  [32 * 16 * 4096];    // K=256, N=4096
__device__ __align__(16) bf16 g_Wd1P [2 * 128 * 4096];    // K=2048, N=256
__device__ __align__(16) bf16 g_Wd2P [32 * 16 * 4096];    // K=256, N=4096
__device__ __align__(16) bf16 g_WcP  [1 * 64 * 4096];     // K=1024, N=32 (pad 128)

__device__ __forceinline__ bf16* packSel(int i) {
    switch (i) {
        case 0: return g_Xp;   case 1: return g_ATTp; case 2: return g_COMPp;
        case 3: return g_HIDp; case 4: return g_GENp; case 5: return g_WqP;
        case 6: return g_WkP;  case 7: return g_WvP;  case 8: return g_WoP;
        case 9: return g_WgP;  case 10: return g_Wd1P; case 11: return g_Wd2P;
        default: return g_WcP;
    }
}

// ---------------------------------------------------------------------------
// PTX helpers
// ---------------------------------------------------------------------------
__device__ __forceinline__ u32 smem_u32(const void* p) {
    u32 a;
    asm("{ .reg .u64 t; cvta.to.shared.u64 t, %1; cvt.u32.u64 %0, t; }" : "=r"(a) : "l"(p));
    return a;
}
__device__ __forceinline__ void ldsm_x4(u32* r, u32 addr) {
    asm volatile("ldmatrix.sync.aligned.m8n8.x4.shared.b16 {%0,%1,%2,%3}, [%4];"
                 : "=r"(r[0]), "=r"(r[1]), "=r"(r[2]), "=r"(r[3]) : "r"(addr));
}
__device__ __forceinline__ void ldsm_x4_t(u32* r, u32 addr) {
    asm volatile("ldmatrix.sync.aligned.m8n8.x4.trans.shared.b16 {%0,%1,%2,%3}, [%4];"
                 : "=r"(r[0]), "=r"(r[1]), "=r"(r[2]), "=r"(r[3]) : "r"(addr));
}
__device__ __forceinline__ void mma_bf16(float* c, const u32* a, const u32* b) {
    asm volatile(
        "mma.sync.aligned.m16n8k16.row.col.f32.bf16.bf16.f32 "
        "{%0,%1,%2,%3}, {%4,%5,%6,%7}, {%8,%9}, {%0,%1,%2,%3};"
        : "+f"(c[0]), "+f"(c[1]), "+f"(c[2]), "+f"(c[3])
        : "r"(a[0]), "r"(a[1]), "r"(a[2]), "r"(a[3]), "r"(b[0]), "r"(b[1]));
}
#define MBAR_INIT(addr, cnt) \
    asm volatile("mbarrier.init.shared.b64 [%0], %1;" :: "r"(addr), "r"(cnt) : "memory")
#define MBAR_EXPECT_TX(addr, tx) \
    asm volatile("mbarrier.arrive.expect_tx.shared.b64 _, [%0], %1;" :: "r"(addr), "r"((u32)(tx)) : "memory")
#define MBAR_WAIT(addr, parity) do {                                           \
    u32 _m = (addr); u32 _p = (parity); u32 _done;                             \
    asm volatile("{\n\t.reg .pred p;\n\t"                                      \
        "mbarrier.try_wait.parity.acquire.cta.shared::cta.b64 p, [%1], %2;\n\t"\
        "selp.b32 %0, 1, 0, p;\n\t}" : "=r"(_done) : "r"(_m), "r"(_p) : "memory"); \
    if (!_done) {                                                              \
        asm volatile("{\n\t.reg .pred P1;\n\t"                                 \
            "WL_%=:\n\t"                                                       \
            "mbarrier.try_wait.parity.acquire.cta.shared::cta.b64 P1, [%0], %1, 0x989680;\n\t" \
            "@P1 bra.uni WD_%=;\n\t"                                           \
            "bra.uni WL_%=;\n\t"                                               \
            "WD_%=:\n\t}" :: "r"(_m), "r"(_p) : "memory");                     \
    } } while (0)
#define CP_BULK(dst, src, bytes, mbar) \
    asm volatile("cp.async.bulk.shared::cluster.global.mbarrier::complete_tx::bytes [%0], [%1], %2, [%3];" \
                 :: "r"(dst), "l"(src), "r"((u32)(bytes)), "r"(mbar) : "memory")

__device__ __forceinline__ void split2(float v0, float v1, __nv_bfloat162& h, __nv_bfloat162& l) {
    h = __floats2bfloat162_rn(v0, v1);
    l = __floats2bfloat162_rn(v0 - __bfloat162float(h.x), v1 - __bfloat162float(h.y));
}

// store an (even) column pair into a packed-A image
__device__ __forceinline__ void packA_store2(bf16* dst, int NCk, int rowA, int colA,
                                             float v0, float v1) {
    int rB = rowA >> 7, r = rowA & 127;
    int chunk = colA >> 4;
    int half = (colA >> 3) & 1;
    int halfS = half ^ ((r >> 2) & 1);
    size_t off = ((size_t)rB * NCk + chunk) * 8192 + r * 32 + (halfS << 4) + (colA & 7) * 2;
    __nv_bfloat162 h, l;
    split2(v0, v1, h, l);
    *(__nv_bfloat162*)((char*)dst + off)        = h;
    *(__nv_bfloat162*)((char*)dst + off + 4096) = l;
}

// ---------------------------------------------------------------------------
// prep_packA: fp32 row-major (M x Kd) -> packed hi/lo A image
// ---------------------------------------------------------------------------
__global__ __launch_bounds__(256) void prep_packA(
    const float* __restrict__ srcIn, int srcSel, int dstSel, int M, int Kd)
{
    const float* src = (srcSel >= 0) ? scratch_ptr(srcSel) : srcIn;
    bf16* dst = packSel(dstSel);
    const int perRow = Kd >> 3;
    const int NCk = Kd >> 4;
    const int total = M * perRow;
    for (int gid = blockIdx.x * 256 + threadIdx.x; gid < total; gid += gridDim.x * 256) {
        int m = gid / perRow, gs = gid - m * perRow;
        int k0 = gs << 3;
        int chunk = k0 >> 4, half = (k0 >> 3) & 1;
        int rB = m >> 7, r = m & 127;
        int halfS = half ^ ((r >> 2) & 1);
        const float* s = src + (size_t)m * Kd + k0;
        float4 va = *(const float4*)s;
        float4 vb = *(const float4*)(s + 4);
        __nv_bfloat162 h0, l0, h1, l1, h2, l2, h3, l3;
        split2(va.x, va.y, h0, l0); split2(va.z, va.w, h1, l1);
        split2(vb.x, vb.y, h2, l2); split2(vb.z, vb.w, h3, l3);
        uint4 hv, lv;
        hv.x = *(u32*)&h0; hv.y = *(u32*)&h1; hv.z = *(u32*)&h2; hv.w = *(u32*)&h3;
        lv.x = *(u32*)&l0; lv.y = *(u32*)&l1; lv.z = *(u32*)&l2; lv.w = *(u32*)&l3;
        char* base = (char*)dst + ((size_t)rB * NCk + chunk) * 8192 + r * 32 + (halfS << 4);
        *(uint4*)base          = hv;
        *(uint4*)(base + 4096) = lv;
    }
}

// ---------------------------------------------------------------------------
// prep_packB: fp32 row-major (Kd x Nd) -> packed hi/lo B image (pad to NT*128)
// ---------------------------------------------------------------------------
__global__ __launch_bounds__(256) void prep_packB(
    const float* __restrict__ src, int dstSel, int Kd, int Nd, int NT)
{
    bf16* dst = packSel(dstSel);
    const int perRow = NT << 4;
    const int NCk = Kd >> 4;
    const int total = Kd * perRow;
    for (int gid = blockIdx.x * 256 + threadIdx.x; gid < total; gid += gridDim.x * 256) {
        int k = gid / perRow, gs = gid - k * perRow;
        int n0 = gs << 3;
        int nt = n0 >> 7, gg = (n0 >> 3) & 15;
        int pos = (gg + (k & 15)) & 15;
        float vv[8];
        #pragma unroll
        for (int j = 0; j < 8; j++) {
            int n = n0 + j;
            vv[j] = (n < Nd) ? src[(size_t)k * Nd + n] : 0.f;
        }
        __nv_bfloat162 h0, l0, h1, l1, h2, l2, h3, l3;
        split2(vv[0], vv[1], h0, l0); split2(vv[2], vv[3], h1, l1);
        split2(vv[4], vv[5], h2, l2); split2(vv[6], vv[7], h3, l3);
        uint4 hv, lv;
        hv.x = *(u32*)&h0; hv.y = *(u32*)&h1; hv.z = *(u32*)&h2; hv.w = *(u32*)&h3;
        lv.x = *(u32*)&l0; lv.y = *(u32*)&l1; lv.z = *(u32*)&l2; lv.w = *(u32*)&l3;
        char* base = (char*)dst + ((size_t)nt * NCk + (k >> 4)) * 8192 + (k & 15) * 256 + pos * 16;
        *(uint4*)base          = hv;
        *(uint4*)(base + 4096) = lv;
    }
}

// ---------------------------------------------------------------------------
// bulk_gemm: C[128x128 tile grid] = A @ B via split-bf16 HMMA.
// 4-stage cp.async.bulk pipeline: 2 bulk ops per chunk (A 8KB, B 8KB).
// mode 0: fp32 row-major (+bias). mode 1: QKV scatter. mode 2: packed COMP.
// ---------------------------------------------------------------------------
__global__ __launch_bounds__(256, 2) void bulk_gemm(
    int aSel, int bSel,
    const float* __restrict__ b0p, const float* __restrict__ b1p,
    const float* __restrict__ b2p,
    float* __restrict__ Cout, int dstC, int NCk, int Nout, int mode)
{
    extern __shared__ __align__(128) unsigned char smp[];   // 4 x 16KB stages
    __shared__ __align__(8) u64 s_mbar[4];

    const int tid = threadIdx.x;
    const int wid = tid >> 5, lane = tid & 31;
    const int wm = wid & 3, wn = wid >> 2;
    const int m0 = wm * 32;
    const int bx = blockIdx.x, by = blockIdx.y;

    const unsigned char* aPack = (const unsigned char*)packSel(aSel);
    const unsigned char* bPack;
    const float* bias;
    float* C = nullptr;
    int ntl;
    if (mode == 1) {
        int t = bx >> 3; ntl = bx & 7;
        bPack = (const unsigned char*)packSel(5 + t);
        bias = (t == 0) ? b0p : ((t == 1) ? b1p : b2p);
        C    = (t == 0) ? g_Q : ((t == 1) ? g_K : g_V);
    } else {
        bPack = (const unsigned char*)packSel(bSel);
        bias = b0p; ntl = bx;
        if (mode == 0) C = (dstC >= 0) ? scratch_ptr(dstC) : Cout;
    }

    const u32 smbase = smem_u32(smp);
    const u32 mbase  = smem_u32(&s_mbar[0]);

    if (tid == 0) {
        #pragma unroll
        for (int s = 0; s < 4; s++) MBAR_INIT(mbase + s * 8, 1);
    }
    __syncthreads();

    const size_t aBase = (size_t)by * NCk * 8192;
    const size_t bBase = (size_t)ntl * NCk * 8192;

    // prologue: issue chunks 0..2
    if (tid == 0) {
        #pragma unroll
        for (int c = 0; c < 3; c++) {
            u32 fb = mbase + (c & 3) * 8;
            u32 dst = smbase + (c & 3) * 16384;
            MBAR_EXPECT_TX(fb, 16384);
            CP_BULK(dst,        aPack + aBase + (size_t)c * 8192, 8192, fb);
            CP_BULK(dst + 8192, bPack + bBase + (size_t)c * 8192, 8192, fb);
        }
    }

    // lane addressing
    const int g = lane >> 3, r = lane & 7;
    const int a_row = ((g & 1) << 3) + r;
    const int halfA = g >> 1;            // 0/1 (8-elem half)
    const int b_row = ((g & 1) << 3) + r;
    const int b_gadd = g >> 1;           // granule offset within 16-col pair

    float acc[2][8][4];
    #pragma unroll
    for (int mf = 0; mf < 2; mf++)
        #pragma unroll
        for (int nf = 0; nf < 8; nf++)
            #pragma unroll
            for (int i = 0; i < 4; i++) acc[mf][nf][i] = 0.f;

    u32 phases = 0;
    for (int c = 0; c < NCk; c++) {
        const int s = c & 3;
        MBAR_WAIT(mbase + s * 8, (phases >> s) & 1);
        phases ^= (1u << s);

        const u32 stb = smbase + s * 16384;

        u32 afh[2][4], afl[2][4];
        #pragma unroll
        for (int mf = 0; mf < 2; mf++) {
            int R = m0 + mf * 16 + a_row;
            u32 aoff = R * 32 + (((u32)halfA ^ ((R >> 2) & 1)) << 4);
            ldsm_x4(afh[mf], stb + aoff);
            ldsm_x4(afl[mf], stb + 4096 + aoff);
        }
        #pragma unroll
        for (int nf2 = 0; nf2 < 4; nf2++) {
            int g16 = wn * 8 + nf2 * 2 + b_gadd;
            u32 boff = b_row * 256 + (((g16 + b_row) & 15) << 4);
            u32 bh4[4], bl4[4];
            ldsm_x4_t(bh4, stb + 8192  + boff);
            ldsm_x4_t(bl4, stb + 12288 + boff);
            #pragma unroll
            for (int mf = 0; mf < 2; mf++) {
                mma_bf16(acc[mf][nf2 * 2 + 0], afh[mf], bh4 + 0);
                mma_bf16(acc[mf][nf2 * 2 + 1], afh[mf], bh4 + 2);
                mma_bf16(acc[mf][nf2 * 2 + 0], afh[mf], bl4 + 0);
                mma_bf16(acc[mf][nf2 * 2 + 1], afh[mf], bl4 + 2);
                mma_bf16(acc[mf][nf2 * 2 + 0], afl[mf], bh4 + 0);
                mma_bf16(acc[mf][nf2 * 2 + 1], afl[mf], bh4 + 2);
            }
        }
        __syncthreads();
        if (tid == 0 && c + 3 < NCk) {
            int cn = c + 3;
            u32 fb = mbase + (cn & 3) * 8;
            u32 dst = smbase + (cn & 3) * 16384;
            MBAR_EXPECT_TX(fb, 16384);
            CP_BULK(dst,        aPack + aBase + (size_t)cn * 8192, 8192, fb);
            CP_BULK(dst + 8192, bPack + bBase + (size_t)cn * 8192, 8192, fb);
        }
    }

    // ---- epilogue ----
    #pragma unroll
    for (int mf = 0; mf < 2; mf++) {
        #pragma unroll
        for (int nf = 0; nf < 8; nf++) {
            int mrow = by * 128 + m0 + mf * 16 + (lane >> 2);
            int ncol = ntl * 128 + wn * 64 + nf * 8 + (lane & 3) * 2;
            float bv0 = bias ? bias[ncol] : 0.f;
            float bv1 = bias ? bias[ncol + 1] : 0.f;
            #pragma unroll
            for (int half = 0; half < 2; half++) {
                int mr = mrow + half * 8;
                float v0 = acc[mf][nf][half * 2 + 0] + bv0;
                float v1 = acc[mf][nf][half * 2 + 1] + bv1;
                if (mode == 1) {
                    int bb = mr >> 6, ss = mr & 63;
                    int h = ncol >> 6, d = ncol & 63;
                    float* p = C + ((((size_t)bb * NH + h) * SEQ + ss) * HD) + d;
                    p[0] = v0; p[1] = v1;
                } else if (mode == 0) {
                    float* p = C + (size_t)mr * Nout + ncol;
                    *(float2*)p = make_float2(v0, v1);
                } else {
                    if (ncol < HC)
                        packA_store2(g_COMPp, 128, mr >> 6, ((mr & 63) << 5) + ncol, v0, v1);
                }
            }
        }
    }
}

// ---------------------------------------------------------------------------
// silu + LN -> packed-A image (layout 1: colA=i; layout 2: rowA=row*16+(i>>8))
// ---------------------------------------------------------------------------
__global__ __launch_bounds__(256) void silu_ln_kernel(
    const float* __restrict__ g, const float* __restrict__ be,
    int N, int srcIdx, int outSel, int NCkOut, int layout)
{
    const float* in = scratch_ptr(srcIdx);
    bf16* outp = packSel(outSel);

    __shared__ float hs[4096];
    __shared__ float red[2][8];

    const int row = blockIdx.x;
    const int tid = threadIdx.x;
    const float* pin = in + (size_t)row * N;

    float sum = 0.f, sq = 0.f;
    for (int i = tid; i < N; i += 256) {
        float y = pin[i];
        float h = y / (1.f + expf(-y));
        hs[i] = h;
        sum += h;
        sq  += h * h;
    }
    #pragma unroll
    for (int off = 16; off > 0; off >>= 1) {
        sum += __shfl_xor_sync(0xffffffffu, sum, off);
        sq  += __shfl_xor_sync(0xffffffffu, sq,  off);
    }
    if ((tid & 31) == 0) { red[0][tid >> 5] = sum; red[1][tid >> 5] = sq; }
    __syncthreads();
    if (tid < 32) {
        float s = (tid < 8) ? red[0][tid] : 0.f;
        float q = (tid < 8) ? red[1][tid] : 0.f;
        #pragma unroll
        for (int off = 4; off > 0; off >>= 1) {
            s += __shfl_xor_sync(0xffffffffu, s, off);
            q += __shfl_xor_sync(0xffffffffu, q, off);
        }
        if (tid == 0) { red[0][0] = s; red[1][0] = q; }
    }
    __syncthreads();
    const float mean = red[0][0] / (float)N;
    const float var  = red[1][0] / (float)N - mean * mean;
    const float inv  = rsqrtf(var + LN_EPS);

    for (int i = tid * 2; i < N; i += 512) {
        float v0 = (hs[i] - mean) * inv * g[i] + be[i];
        float v1 = (hs[i + 1] - mean) * inv * g[i + 1] + be[i + 1];
        int rowA, colA;
        if (layout == 1) { rowA = row; colA = i; }
        else             { rowA = row * 16 + (i >> 8); colA = i & 255; }
        packA_store2(outp, NCkOut, rowA, colA, v0, v1);
    }
}

// ---------------------------------------------------------------------------
// Attention: softmax(q@k^T*scale + bias) @ v -> g_ATT fp32 (B,S,E)
// ---------------------------------------------------------------------------
__global__ __launch_bounds__(256) void attn_kernel()
{
    __shared__ float ks[64][65];
    __shared__ float vs[64][65];
    __shared__ float ps[8][64];

    const int bh = blockIdx.x;
    const int b = bh >> 4, h = bh & 15;
    const int tid = threadIdx.x;
    const float* kp = g_K + (size_t)bh * (SEQ * HD);
    const float* vp = g_V + (size_t)bh * (SEQ * HD);
    const float* qp = g_Q + (size_t)bh * (SEQ * HD);
    const float* bp = g_BIAS + (size_t)bh * (SEQ * SEQ);

    #pragma unroll
    for (int p = 0; p < 4; p++) {
        int idx = tid + 256 * p;
        int s = idx >> 4, d4 = (idx & 15) * 4;
        float4 kv = *(const float4*)(kp + s * HD + d4);
        ks[s][d4] = kv.x; ks[s][d4 + 1] = kv.y; ks[s][d4 + 2] = kv.z; ks[s][d4 + 3] = kv.w;
        float4 vv = *(const float4*)(vp + s * HD + d4);
        vs[s][d4] = vv.x; vs[s][d4 + 1] = vv.y; vs[s][d4 + 2] = vv.z; vs[s][d4 + 3] = vv.w;
    }
    __syncthreads();

    const int w = tid >> 5, lane = tid & 31;
    const float scale = 0.125f;

    for (int rr = w * 8; rr < w * 8 + 8; rr++) {
        const float* q = qp + rr * HD;
        float dot0 = 0.f, dot1 = 0.f;
        #pragma unroll
        for (int k = 0; k < 64; k++) {
            float qk = __ldg(q + k);
            dot0 += qk * ks[lane][k];
            dot1 += qk * ks[lane + 32][k];
        }
        float acc0 = dot0 * scale + bp[rr * 64 + lane];
        float acc1 = dot1 * scale + bp[rr * 64 + lane + 32];

        float m = fmaxf(acc0, acc1);
        #pragma unroll
        for (int off = 16; off > 0; off >>= 1)
            m = fmaxf(m, __shfl_xor_sync(0xffffffffu, m, off));
        float e0 = __expf(acc0 - m), e1 = __expf(acc1 - m);
        float s = e0 + e1;
        #pragma unroll
        for (int off = 16; off > 0; off >>= 1)
            s += __shfl_xor_sync(0xffffffffu, s, off);
        float invs = 1.f / s;

        __syncwarp();
        ps[w][lane]      = e0 * invs;
        ps[w][lane + 32] = e1 * invs;
        __syncwarp();

        float o0 = 0.f, o1 = 0.f;
        #pragma unroll
        for (int j = 0; j < 64; j++) {
            float pj = ps[w][j];
            o0 += pj * vs[j][lane];
            o1 += pj * vs[j][lane + 32];
        }
        float* op = g_ATT + ((size_t)(b * SEQ + rr) * EMB) + h * HD;
        op[lane]      = o0;
        op[lane + 32] = o1;
    }
}

// ---------------------------------------------------------------------------
// kernel_launch
// ---------------------------------------------------------------------------
extern "C" void kernel_launch(void* const* d_in, const int* in_sizes, int n_in,
                              void* d_out, int out_size)
{
    const float* x   = (const float*)d_in[0];
    const float* Wq  = (const float*)d_in[1];
    const float* bq  = (const float*)d_in[2];
    const float* Wk  = (const float*)d_in[3];
    const float* bk  = (const float*)d_in[4];
    const float* Wv  = (const float*)d_in[5];
    const float* bv  = (const float*)d_in[6];
    const float* Wo  = (const float*)d_in[7];
    const float* bo  = (const float*)d_in[8];
    const float* Wc  = (const float*)d_in[9];
    const float* Wd1 = (const float*)d_in[10];
    const float* bd1 = (const float*)d_in[11];
    const float* g1  = (const float*)d_in[12];
    const float* be1 = (const float*)d_in[13];
    const float* Wd2 = (const float*)d_in[14];
    const float* bd2 = (const float*)d_in[15];
    const float* g2  = (const float*)d_in[16];
    const float* be2 = (const float*)d_in[17];
    const float* Wg  = (const float*)d_in[18];

    cudaFuncSetAttribute(bulk_gemm, cudaFuncAttributeMaxDynamicSharedMemorySize, 65536);

    // ---- packing ----
    prep_packA<<<4096, 256>>>(x, -1, 0, BATCH * SEQ, EMB);
    prep_packB<<<128, 256>>>(Wq,  5, EMB, EMB, 8);
    prep_packB<<<128, 256>>>(Wk,  6, EMB, EMB, 8);
    prep_packB<<<128, 256>>>(Wv,  7, EMB, EMB, 8);
    prep_packB<<<128, 256>>>(Wo,  8, EMB, EMB, 8);
    prep_packB<<<64,  256>>>(Wg,  9, GS, SEQ * SEQ, 32);
    prep_packB<<<64,  256>>>(Wd1, 10, SEQ * HC, HS, 2);
    prep_packB<<<64,  256>>>(Wd2, 11, HS, GS * NH, 32);
    prep_packB<<<32,  256>>>(Wc,  12, EMB, HC, 1);

    // ---- QKV fused (mode 1): grid (3 tensors x 8 ntiles, 512 row-blocks) ----
    bulk_gemm<<<dim3(24, 512), 256, 65536>>>(
        0, -1, bq, bk, bv, nullptr, -1, 64, EMB, 1);

    // ---- compress (mode 2 -> packed COMP) ----
    bulk_gemm<<<dim3(1, 512), 256, 65536>>>(
        0, 12, nullptr, nullptr, nullptr, nullptr, -1, 64, HC, 2);

    // ---- dense1 -> g_T1 fp32 ----
    bulk_gemm<<<dim3(2, 8), 256, 65536>>>(
        2, 10, bd1, nullptr, nullptr, nullptr, 3, 128, HS, 0);
    silu_ln_kernel<<<BATCH, 256>>>(g1, be1, HS, 3, 3, 16, 1);

    // ---- dense2 -> g_T2 fp32 ----
    bulk_gemm<<<dim3(32, 8), 256, 65536>>>(
        3, 11, bd2, nullptr, nullptr, nullptr, 4, 16, GS * NH, 0);
    silu_ln_kernel<<<BATCH, 256>>>(g2, be2, GS * NH, 4, 4, 16, 2);

    // ---- bias-gen -> g_BIAS fp32 ----
    bulk_gemm<<<dim3(32, 128), 256, 65536>>>(
        4, 9, nullptr, nullptr, nullptr, nullptr, 5, 16, SEQ * SEQ, 0);

    // ---- attention -> g_ATT fp32 ----
    attn_kernel<<<BATCH * NH, 256>>>();

    // ---- repack ATT, then output projection -> d_out ----
    prep_packA<<<4096, 256>>>(nullptr, 6, 1, BATCH * SEQ, EMB);
    bulk_gemm<<<dim3(8, 512), 256, 65536>>>(
        1, 8, bo, nullptr, nullptr, (float*)d_out, -1, 64, EMB, 0);
}

// round 9
// speedup vs baseline: 2.6371x; 1.0028x over previous
#include <cuda_runtime.h>
#include <cuda_bf16.h>
#include <math.h>

typedef unsigned int u32;
typedef unsigned long long u64;
typedef __nv_bfloat16 bf16;

// ---------------------------------------------------------------------------
// Problem constants
// ---------------------------------------------------------------------------
#define BATCH 1024
#define SEQ   64
#define EMB   1024
#define NH    16
#define HD    64
#define HC    32
#define HS    256
#define GS    256
#define LN_EPS 1e-3f

// ---------------------------------------------------------------------------
// fp32 scratch
// ---------------------------------------------------------------------------
__device__ float g_Q   [BATCH * NH * SEQ * HD];
__device__ float g_K   [BATCH * NH * SEQ * HD];
__device__ float g_V   [BATCH * NH * SEQ * HD];
__device__ float g_T1  [BATCH * HS];
__device__ float g_T2  [BATCH * GS * NH];
__device__ float g_BIAS[BATCH * NH * SEQ * SEQ];

__device__ __forceinline__ float* scratch_ptr(int which) {
    switch (which) {
        case 0: return g_Q;  case 1: return g_K;   case 2: return g_V;
        case 3: return g_T1; case 4: return g_T2;  default: return g_BIAS;
    }
}

// ---------------------------------------------------------------------------
// Packed tile images: [rowBlk/ntile][chunk] of 8192B = [hi 4KB | lo 4KB]
// A tile: 128 rows x 16 k (row r at r*32, halves swizzled: half ^= (r>>2)&1)
// B tile: 16 k x 128 n (row k at k*256, granule g at ((g + k)&15)*16)
// ---------------------------------------------------------------------------
__device__ __align__(16) bf16 g_Xp   [512 * 64 * 4096];   // X: M=65536, K=1024
__device__ __align__(16) bf16 g_ATTp [512 * 64 * 4096];
__device__ __align__(16) bf16 g_COMPp[8 * 128 * 4096];    // M=1024, K=2048
__device__ __align__(16) bf16 g_HIDp [8 * 16 * 4096];     // M=1024, K=256
__device__ __align__(16) bf16 g_GENp [128 * 16 * 4096];   // M=16384, K=256
__device__ __align__(16) bf16 g_WqP  [8 * 64 * 4096];
__device__ __align__(16) bf16 g_WkP  [8 * 64 * 4096];
__device__ __align__(16) bf16 g_WvP  [8 * 64 * 4096];
__device__ __align__(16) bf16 g_WoP  [8 * 64 * 4096];
__device__ __align__(16) bf16 g_WgP  [32 * 16 * 4096];    // K=256, N=4096
__device__ __align__(16) bf16 g_Wd1P [2 * 128 * 4096];    // K=2048, N=256
__device__ __align__(16) bf16 g_Wd2P [32 * 16 * 4096];    // K=256, N=4096
__device__ __align__(16) bf16 g_WcP  [1 * 64 * 4096];     // K=1024, N=32 (pad 128)

__device__ __forceinline__ bf16* packSel(int i) {
    switch (i) {
        case 0: return g_Xp;   case 1: return g_ATTp; case 2: return g_COMPp;
        case 3: return g_HIDp; case 4: return g_GENp; case 5: return g_WqP;
        case 6: return g_WkP;  case 7: return g_WvP;  case 8: return g_WoP;
        case 9: return g_WgP;  case 10: return g_Wd1P; case 11: return g_Wd2P;
        default: return g_WcP;
    }
}

// ---------------------------------------------------------------------------
// PTX helpers
// ---------------------------------------------------------------------------
__device__ __forceinline__ u32 smem_u32(const void* p) {
    u32 a;
    asm("{ .reg .u64 t; cvta.to.shared.u64 t, %1; cvt.u32.u64 %0, t; }" : "=r"(a) : "l"(p));
    return a;
}
__device__ __forceinline__ void ldsm_x4(u32* r, u32 addr) {
    asm volatile("ldmatrix.sync.aligned.m8n8.x4.shared.b16 {%0,%1,%2,%3}, [%4];"
                 : "=r"(r[0]), "=r"(r[1]), "=r"(r[2]), "=r"(r[3]) : "r"(addr));
}
__device__ __forceinline__ void ldsm_x4_t(u32* r, u32 addr) {
    asm volatile("ldmatrix.sync.aligned.m8n8.x4.trans.shared.b16 {%0,%1,%2,%3}, [%4];"
                 : "=r"(r[0]), "=r"(r[1]), "=r"(r[2]), "=r"(r[3]) : "r"(addr));
}
__device__ __forceinline__ void mma_bf16(float* c, const u32* a, const u32* b) {
    asm volatile(
        "mma.sync.aligned.m16n8k16.row.col.f32.bf16.bf16.f32 "
        "{%0,%1,%2,%3}, {%4,%5,%6,%7}, {%8,%9}, {%0,%1,%2,%3};"
        : "+f"(c[0]), "+f"(c[1]), "+f"(c[2]), "+f"(c[3])
        : "r"(a[0]), "r"(a[1]), "r"(a[2]), "r"(a[3]), "r"(b[0]), "r"(b[1]));
}
#define MBAR_INIT(addr, cnt) \
    asm volatile("mbarrier.init.shared.b64 [%0], %1;" :: "r"(addr), "r"(cnt) : "memory")
#define MBAR_EXPECT_TX(addr, tx) \
    asm volatile("mbarrier.arrive.expect_tx.shared.b64 _, [%0], %1;" :: "r"(addr), "r"((u32)(tx)) : "memory")
#define MBAR_WAIT(addr, parity) do {                                           \
    u32 _m = (addr); u32 _p = (parity); u32 _done;                             \
    asm volatile("{\n\t.reg .pred p;\n\t"                                      \
        "mbarrier.try_wait.parity.acquire.cta.shared::cta.b64 p, [%1], %2;\n\t"\
        "selp.b32 %0, 1, 0, p;\n\t}" : "=r"(_done) : "r"(_m), "r"(_p) : "memory"); \
    if (!_done) {                                                              \
        asm volatile("{\n\t.reg .pred P1;\n\t"                                 \
            "WL_%=:\n\t"                                                       \
            "mbarrier.try_wait.parity.acquire.cta.shared::cta.b64 P1, [%0], %1, 0x989680;\n\t" \
            "@P1 bra.uni WD_%=;\n\t"                                           \
            "bra.uni WL_%=;\n\t"                                               \
            "WD_%=:\n\t}" :: "r"(_m), "r"(_p) : "memory");                     \
    } } while (0)
#define CP_BULK(dst, src, bytes, mbar) \
    asm volatile("cp.async.bulk.shared::cluster.global.mbarrier::complete_tx::bytes [%0], [%1], %2, [%3];" \
                 :: "r"(dst), "l"(src), "r"((u32)(bytes)), "r"(mbar) : "memory")

__device__ __forceinline__ void split2(float v0, float v1, __nv_bfloat162& h, __nv_bfloat162& l) {
    h = __floats2bfloat162_rn(v0, v1);
    l = __floats2bfloat162_rn(v0 - __bfloat162float(h.x), v1 - __bfloat162float(h.y));
}

// store an (even) column pair into a packed-A image
__device__ __forceinline__ void packA_store2(bf16* dst, int NCk, int rowA, int colA,
                                             float v0, float v1) {
    int rB = rowA >> 7, r = rowA & 127;
    int chunk = colA >> 4;
    int half = (colA >> 3) & 1;
    int halfS = half ^ ((r >> 2) & 1);
    size_t off = ((size_t)rB * NCk + chunk) * 8192 + r * 32 + (halfS << 4) + (colA & 7) * 2;
    __nv_bfloat162 h, l;
    split2(v0, v1, h, l);
    *(__nv_bfloat162*)((char*)dst + off)        = h;
    *(__nv_bfloat162*)((char*)dst + off + 4096) = l;
}

// ---------------------------------------------------------------------------
// prep_packA: fp32 row-major (M x Kd) -> packed hi/lo A image
// ---------------------------------------------------------------------------
__global__ __launch_bounds__(256) void prep_packA(
    const float* __restrict__ src, int dstSel, int M, int Kd)
{
    bf16* dst = packSel(dstSel);
    const int perRow = Kd >> 3;
    const int NCk = Kd >> 4;
    const int total = M * perRow;
    for (int gid = blockIdx.x * 256 + threadIdx.x; gid < total; gid += gridDim.x * 256) {
        int m = gid / perRow, gs = gid - m * perRow;
        int k0 = gs << 3;
        int chunk = k0 >> 4, half = (k0 >> 3) & 1;
        int rB = m >> 7, r = m & 127;
        int halfS = half ^ ((r >> 2) & 1);
        const float* s = src + (size_t)m * Kd + k0;
        float4 va = *(const float4*)s;
        float4 vb = *(const float4*)(s + 4);
        __nv_bfloat162 h0, l0, h1, l1, h2, l2, h3, l3;
        split2(va.x, va.y, h0, l0); split2(va.z, va.w, h1, l1);
        split2(vb.x, vb.y, h2, l2); split2(vb.z, vb.w, h3, l3);
        uint4 hv, lv;
        hv.x = *(u32*)&h0; hv.y = *(u32*)&h1; hv.z = *(u32*)&h2; hv.w = *(u32*)&h3;
        lv.x = *(u32*)&l0; lv.y = *(u32*)&l1; lv.z = *(u32*)&l2; lv.w = *(u32*)&l3;
        char* base = (char*)dst + ((size_t)rB * NCk + chunk) * 8192 + r * 32 + (halfS << 4);
        *(uint4*)base          = hv;
        *(uint4*)(base + 4096) = lv;
    }
}

// ---------------------------------------------------------------------------
// prep_packB: fp32 row-major (Kd x Nd) -> packed hi/lo B image (pad to NT*128)
// ---------------------------------------------------------------------------
__global__ __launch_bounds__(256) void prep_packB(
    const float* __restrict__ src, int dstSel, int Kd, int Nd, int NT)
{
    bf16* dst = packSel(dstSel);
    const int perRow = NT << 4;
    const int NCk = Kd >> 4;
    const int total = Kd * perRow;
    for (int gid = blockIdx.x * 256 + threadIdx.x; gid < total; gid += gridDim.x * 256) {
        int k = gid / perRow, gs = gid - k * perRow;
        int n0 = gs << 3;
        int nt = n0 >> 7, gg = (n0 >> 3) & 15;
        int pos = (gg + (k & 15)) & 15;
        float vv[8];
        #pragma unroll
        for (int j = 0; j < 8; j++) {
            int n = n0 + j;
            vv[j] = (n < Nd) ? src[(size_t)k * Nd + n] : 0.f;
        }
        __nv_bfloat162 h0, l0, h1, l1, h2, l2, h3, l3;
        split2(vv[0], vv[1], h0, l0); split2(vv[2], vv[3], h1, l1);
        split2(vv[4], vv[5], h2, l2); split2(vv[6], vv[7], h3, l3);
        uint4 hv, lv;
        hv.x = *(u32*)&h0; hv.y = *(u32*)&h1; hv.z = *(u32*)&h2; hv.w = *(u32*)&h3;
        lv.x = *(u32*)&l0; lv.y = *(u32*)&l1; lv.z = *(u32*)&l2; lv.w = *(u32*)&l3;
        char* base = (char*)dst + ((size_t)nt * NCk + (k >> 4)) * 8192 + (k & 15) * 256 + pos * 16;
        *(uint4*)base          = hv;
        *(uint4*)(base + 4096) = lv;
    }
}

// ---------------------------------------------------------------------------
// bulk_gemm: C = A @ B via split-bf16 HMMA. 4-stage cp.async.bulk pipeline,
// chunk-PAIR iteration (one syncthreads / two chunks).
// mode 0: fp32 row-major (+bias). mode 1: QKV scatter. mode 2: packed COMP.
// ---------------------------------------------------------------------------
__global__ __launch_bounds__(256, 2) void bulk_gemm(
    int aSel, int bSel,
    const float* __restrict__ b0p, const float* __restrict__ b1p,
    const float* __restrict__ b2p,
    float* __restrict__ Cout, int dstC, int NCk, int Nout, int mode)
{
    extern __shared__ __align__(128) unsigned char smp[];   // 4 x 16KB stages
    __shared__ __align__(8) u64 s_mbar[4];

    const int tid = threadIdx.x;
    const int wid = tid >> 5, lane = tid & 31;
    const int wm = wid & 3, wn = wid >> 2;
    const int m0 = wm * 32;
    const int bx = blockIdx.x, by = blockIdx.y;

    const unsigned char* aPack = (const unsigned char*)packSel(aSel);
    const unsigned char* bPack;
    const float* bias;
    float* C = nullptr;
    int ntl;
    if (mode == 1) {
        int t = bx >> 3; ntl = bx & 7;
        bPack = (const unsigned char*)packSel(5 + t);
        bias = (t == 0) ? b0p : ((t == 1) ? b1p : b2p);
        C    = (t == 0) ? g_Q : ((t == 1) ? g_K : g_V);
    } else {
        bPack = (const unsigned char*)packSel(bSel);
        bias = b0p; ntl = bx;
        if (mode == 0) C = (dstC >= 0) ? scratch_ptr(dstC) : Cout;
    }

    const u32 smbase = smem_u32(smp);
    const u32 mbase  = smem_u32(&s_mbar[0]);

    if (tid == 0) {
        #pragma unroll
        for (int s = 0; s < 4; s++) MBAR_INIT(mbase + s * 8, 1);
    }
    __syncthreads();

    const size_t aBase = (size_t)by * NCk * 8192;
    const size_t bBase = (size_t)ntl * NCk * 8192;

    // prologue: fill all 4 stages
    if (tid == 0) {
        #pragma unroll
        for (int c = 0; c < 4; c++) {
            if (c < NCk) {
                u32 fb = mbase + c * 8;
                u32 dst = smbase + c * 16384;
                MBAR_EXPECT_TX(fb, 16384);
                CP_BULK(dst,        aPack + aBase + (size_t)c * 8192, 8192, fb);
                CP_BULK(dst + 8192, bPack + bBase + (size_t)c * 8192, 8192, fb);
            }
        }
    }

    // lane addressing
    const int g = lane >> 3, r = lane & 7;
    const int a_row = ((g & 1) << 3) + r;
    const int halfA = g >> 1;
    const int b_row = ((g & 1) << 3) + r;
    const int b_gadd = g >> 1;

    float acc[2][8][4];
    #pragma unroll
    for (int mf = 0; mf < 2; mf++)
        #pragma unroll
        for (int nf = 0; nf < 8; nf++)
            #pragma unroll
            for (int i = 0; i < 4; i++) acc[mf][nf][i] = 0.f;

    auto compute_chunk = [&](u32 stb) {
        u32 afh[2][4], afl[2][4];
        #pragma unroll
        for (int mf = 0; mf < 2; mf++) {
            int R = m0 + mf * 16 + a_row;
            u32 aoff = R * 32 + (((u32)halfA ^ ((R >> 2) & 1)) << 4);
            ldsm_x4(afh[mf], stb + aoff);
            ldsm_x4(afl[mf], stb + 4096 + aoff);
        }
        #pragma unroll
        for (int nf2 = 0; nf2 < 4; nf2++) {
            int g16 = wn * 8 + nf2 * 2 + b_gadd;
            u32 boff = b_row * 256 + (((g16 + b_row) & 15) << 4);
            u32 bh4[4], bl4[4];
            ldsm_x4_t(bh4, stb + 8192  + boff);
            ldsm_x4_t(bl4, stb + 12288 + boff);
            #pragma unroll
            for (int mf = 0; mf < 2; mf++) {
                mma_bf16(acc[mf][nf2 * 2 + 0], afh[mf], bh4 + 0);
                mma_bf16(acc[mf][nf2 * 2 + 1], afh[mf], bh4 + 2);
                mma_bf16(acc[mf][nf2 * 2 + 0], afh[mf], bl4 + 0);
                mma_bf16(acc[mf][nf2 * 2 + 1], afh[mf], bl4 + 2);
                mma_bf16(acc[mf][nf2 * 2 + 0], afl[mf], bh4 + 0);
                mma_bf16(acc[mf][nf2 * 2 + 1], afl[mf], bh4 + 2);
            }
        }
    };

    u32 phases = 0;
    for (int c = 0; c < NCk; c += 2) {
        const int s0 = c & 3, s1 = (c + 1) & 3;
        MBAR_WAIT(mbase + s0 * 8, (phases >> s0) & 1);
        phases ^= (1u << s0);
        compute_chunk(smbase + s0 * 16384);
        MBAR_WAIT(mbase + s1 * 8, (phases >> s1) & 1);
        phases ^= (1u << s1);
        compute_chunk(smbase + s1 * 16384);
        __syncthreads();
        if (tid == 0) {
            #pragma unroll
            for (int d = 4; d <= 5; d++) {
                int cn = c + d;
                if (cn < NCk) {
                    u32 fb = mbase + (cn & 3) * 8;
                    u32 dst = smbase + (cn & 3) * 16384;
                    MBAR_EXPECT_TX(fb, 16384);
                    CP_BULK(dst,        aPack + aBase + (size_t)cn * 8192, 8192, fb);
                    CP_BULK(dst + 8192, bPack + bBase + (size_t)cn * 8192, 8192, fb);
                }
            }
        }
    }

    // ---- epilogue ----
    #pragma unroll
    for (int mf = 0; mf < 2; mf++) {
        #pragma unroll
        for (int nf = 0; nf < 8; nf++) {
            int mrow = by * 128 + m0 + mf * 16 + (lane >> 2);
            int ncol = ntl * 128 + wn * 64 + nf * 8 + (lane & 3) * 2;
            float bv0 = bias ? bias[ncol] : 0.f;
            float bv1 = bias ? bias[ncol + 1] : 0.f;
            #pragma unroll
            for (int half = 0; half < 2; half++) {
                int mr = mrow + half * 8;
                float v0 = acc[mf][nf][half * 2 + 0] + bv0;
                float v1 = acc[mf][nf][half * 2 + 1] + bv1;
                if (mode == 1) {
                    int bb = mr >> 6, ss = mr & 63;
                    int h = ncol >> 6, d = ncol & 63;
                    float* p = C + ((((size_t)bb * NH + h) * SEQ + ss) * HD) + d;
                    p[0] = v0; p[1] = v1;
                } else if (mode == 0) {
                    float* p = C + (size_t)mr * Nout + ncol;
                    *(float2*)p = make_float2(v0, v1);
                } else {
                    if (ncol < HC)
                        packA_store2(g_COMPp, 128, mr >> 6, ((mr & 63) << 5) + ncol, v0, v1);
                }
            }
        }
    }
}

// ---------------------------------------------------------------------------
// silu + LN -> packed-A image (layout 1: colA=i; layout 2: rowA=row*16+(i>>8))
// ---------------------------------------------------------------------------
__global__ __launch_bounds__(256) void silu_ln_kernel(
    const float* __restrict__ g, const float* __restrict__ be,
    int N, int srcIdx, int outSel, int NCkOut, int layout)
{
    const float* in = scratch_ptr(srcIdx);
    bf16* outp = packSel(outSel);

    __shared__ float hs[4096];
    __shared__ float red[2][8];

    const int row = blockIdx.x;
    const int tid = threadIdx.x;
    const float* pin = in + (size_t)row * N;

    float sum = 0.f, sq = 0.f;
    for (int i = tid; i < N; i += 256) {
        float y = pin[i];
        float h = y / (1.f + expf(-y));
        hs[i] = h;
        sum += h;
        sq  += h * h;
    }
    #pragma unroll
    for (int off = 16; off > 0; off >>= 1) {
        sum += __shfl_xor_sync(0xffffffffu, sum, off);
        sq  += __shfl_xor_sync(0xffffffffu, sq,  off);
    }
    if ((tid & 31) == 0) { red[0][tid >> 5] = sum; red[1][tid >> 5] = sq; }
    __syncthreads();
    if (tid < 32) {
        float s = (tid < 8) ? red[0][tid] : 0.f;
        float q = (tid < 8) ? red[1][tid] : 0.f;
        #pragma unroll
        for (int off = 4; off > 0; off >>= 1) {
            s += __shfl_xor_sync(0xffffffffu, s, off);
            q += __shfl_xor_sync(0xffffffffu, q, off);
        }
        if (tid == 0) { red[0][0] = s; red[1][0] = q; }
    }
    __syncthreads();
    const float mean = red[0][0] / (float)N;
    const float var  = red[1][0] / (float)N - mean * mean;
    const float inv  = rsqrtf(var + LN_EPS);

    for (int i = tid * 2; i < N; i += 512) {
        float v0 = (hs[i] - mean) * inv * g[i] + be[i];
        float v1 = (hs[i + 1] - mean) * inv * g[i + 1] + be[i + 1];
        int rowA, colA;
        if (layout == 1) { rowA = row; colA = i; }
        else             { rowA = row * 16 + (i >> 8); colA = i & 255; }
        packA_store2(outp, NCkOut, rowA, colA, v0, v1);
    }
}

// ---------------------------------------------------------------------------
// Attention: softmax(q@k^T*scale + bias) @ v -> packed ATT image directly
// ---------------------------------------------------------------------------
__global__ __launch_bounds__(256) void attn_kernel()
{
    __shared__ float ks[64][65];
    __shared__ float vs[64][65];
    __shared__ float ps[8][64];

    const int bh = blockIdx.x;
    const int b = bh >> 4, h = bh & 15;
    const int tid = threadIdx.x;
    const float* kp = g_K + (size_t)bh * (SEQ * HD);
    const float* vp = g_V + (size_t)bh * (SEQ * HD);
    const float* qp = g_Q + (size_t)bh * (SEQ * HD);
    const float* bp = g_BIAS + (size_t)bh * (SEQ * SEQ);

    #pragma unroll
    for (int p = 0; p < 4; p++) {
        int idx = tid + 256 * p;
        int s = idx >> 4, d4 = (idx & 15) * 4;
        float4 kv = *(const float4*)(kp + s * HD + d4);
        ks[s][d4] = kv.x; ks[s][d4 + 1] = kv.y; ks[s][d4 + 2] = kv.z; ks[s][d4 + 3] = kv.w;
        float4 vv = *(const float4*)(vp + s * HD + d4);
        vs[s][d4] = vv.x; vs[s][d4 + 1] = vv.y; vs[s][d4 + 2] = vv.z; vs[s][d4 + 3] = vv.w;
    }
    __syncthreads();

    const int w = tid >> 5, lane = tid & 31;
    const float scale = 0.125f;

    for (int rr = w * 8; rr < w * 8 + 8; rr++) {
        const float* q = qp + rr * HD;
        float dot0 = 0.f, dot1 = 0.f;
        #pragma unroll
        for (int k = 0; k < 64; k++) {
            float qk = __ldg(q + k);
            dot0 += qk * ks[lane][k];
            dot1 += qk * ks[lane + 32][k];
        }
        float acc0 = dot0 * scale + bp[rr * 64 + lane];
        float acc1 = dot1 * scale + bp[rr * 64 + lane + 32];

        float m = fmaxf(acc0, acc1);
        #pragma unroll
        for (int off = 16; off > 0; off >>= 1)
            m = fmaxf(m, __shfl_xor_sync(0xffffffffu, m, off));
        float e0 = __expf(acc0 - m), e1 = __expf(acc1 - m);
        float s = e0 + e1;
        #pragma unroll
        for (int off = 16; off > 0; off >>= 1)
            s += __shfl_xor_sync(0xffffffffu, s, off);
        float invs = 1.f / s;

        __syncwarp();
        ps[w][lane]      = e0 * invs;
        ps[w][lane + 32] = e1 * invs;
        __syncwarp();

        // AV: each lane produces adjacent column pair (2*lane, 2*lane+1)
        float o0 = 0.f, o1 = 0.f;
        #pragma unroll
        for (int j = 0; j < 64; j++) {
            float pj = ps[w][j];
            o0 += pj * vs[j][2 * lane];
            o1 += pj * vs[j][2 * lane + 1];
        }
        packA_store2(g_ATTp, 64, b * SEQ + rr, h * HD + 2 * lane, o0, o1);
    }
}

// ---------------------------------------------------------------------------
// kernel_launch
// ---------------------------------------------------------------------------
extern "C" void kernel_launch(void* const* d_in, const int* in_sizes, int n_in,
                              void* d_out, int out_size)
{
    const float* x   = (const float*)d_in[0];
    const float* Wq  = (const float*)d_in[1];
    const float* bq  = (const float*)d_in[2];
    const float* Wk  = (const float*)d_in[3];
    const float* bk  = (const float*)d_in[4];
    const float* Wv  = (const float*)d_in[5];
    const float* bv  = (const float*)d_in[6];
    const float* Wo  = (const float*)d_in[7];
    const float* bo  = (const float*)d_in[8];
    const float* Wc  = (const float*)d_in[9];
    const float* Wd1 = (const float*)d_in[10];
    const float* bd1 = (const float*)d_in[11];
    const float* g1  = (const float*)d_in[12];
    const float* be1 = (const float*)d_in[13];
    const float* Wd2 = (const float*)d_in[14];
    const float* bd2 = (const float*)d_in[15];
    const float* g2  = (const float*)d_in[16];
    const float* be2 = (const float*)d_in[17];
    const float* Wg  = (const float*)d_in[18];

    cudaFuncSetAttribute(bulk_gemm, cudaFuncAttributeMaxDynamicSharedMemorySize, 65536);

    // ---- packing ----
    prep_packA<<<4096, 256>>>(x, 0, BATCH * SEQ, EMB);
    prep_packB<<<128, 256>>>(Wq,  5, EMB, EMB, 8);
    prep_packB<<<128, 256>>>(Wk,  6, EMB, EMB, 8);
    prep_packB<<<128, 256>>>(Wv,  7, EMB, EMB, 8);
    prep_packB<<<128, 256>>>(Wo,  8, EMB, EMB, 8);
    prep_packB<<<64,  256>>>(Wg,  9, GS, SEQ * SEQ, 32);
    prep_packB<<<64,  256>>>(Wd1, 10, SEQ * HC, HS, 2);
    prep_packB<<<64,  256>>>(Wd2, 11, HS, GS * NH, 32);
    prep_packB<<<32,  256>>>(Wc,  12, EMB, HC, 1);

    // ---- QKV fused (mode 1) ----
    bulk_gemm<<<dim3(24, 512), 256, 65536>>>(
        0, -1, bq, bk, bv, nullptr, -1, 64, EMB, 1);

    // ---- compress (mode 2 -> packed COMP) ----
    bulk_gemm<<<dim3(1, 512), 256, 65536>>>(
        0, 12, nullptr, nullptr, nullptr, nullptr, -1, 64, HC, 2);

    // ---- dense1 -> g_T1 fp32 ----
    bulk_gemm<<<dim3(2, 8), 256, 65536>>>(
        2, 10, bd1, nullptr, nullptr, nullptr, 3, 128, HS, 0);
    silu_ln_kernel<<<BATCH, 256>>>(g1, be1, HS, 3, 3, 16, 1);

    // ---- dense2 -> g_T2 fp32 ----
    bulk_gemm<<<dim3(32, 8), 256, 65536>>>(
        3, 11, bd2, nullptr, nullptr, nullptr, 4, 16, GS * NH, 0);
    silu_ln_kernel<<<BATCH, 256>>>(g2, be2, GS * NH, 4, 4, 16, 2);

    // ---- bias-gen -> g_BIAS fp32 ----
    bulk_gemm<<<dim3(32, 128), 256, 65536>>>(
        4, 9, nullptr, nullptr, nullptr, nullptr, 5, 16, SEQ * SEQ, 0);

    // ---- attention -> packed ATT directly ----
    attn_kernel<<<BATCH * NH, 256>>>();

    // ---- output projection -> d_out ----
    bulk_gemm<<<dim3(8, 512), 256, 65536>>>(
        1, 8, bo, nullptr, nullptr, (float*)d_out, -1, 64, EMB, 0);
}

// round 10
// speedup vs baseline: 2.6444x; 1.0028x over previous
#include <cuda_runtime.h>
#include <cuda_bf16.h>
#include <math.h>

typedef unsigned int u32;
typedef unsigned long long u64;
typedef __nv_bfloat16 bf16;

// ---------------------------------------------------------------------------
// Problem constants
// ---------------------------------------------------------------------------
#define BATCH 1024
#define SEQ   64
#define EMB   1024
#define NH    16
#define HD    64
#define HC    32
#define HS    256
#define GS    256
#define LN_EPS 1e-3f

// ---------------------------------------------------------------------------
// fp32 scratch
// ---------------------------------------------------------------------------
__device__ float g_Q   [BATCH * NH * SEQ * HD];
__device__ float g_K   [BATCH * NH * SEQ * HD];
__device__ float g_V   [BATCH * NH * SEQ * HD];
__device__ float g_T1  [BATCH * HS];
__device__ float g_T2  [BATCH * GS * NH];
__device__ float g_BIAS[BATCH * NH * SEQ * SEQ];

__device__ __forceinline__ float* scratch_ptr(int which) {
    switch (which) {
        case 0: return g_Q;  case 1: return g_K;   case 2: return g_V;
        case 3: return g_T1; case 4: return g_T2;  default: return g_BIAS;
    }
}

// ---------------------------------------------------------------------------
// Packed tile images: [rowBlk/ntile][chunk] of 8192B = [hi 4KB | lo 4KB]
// A tile: 128 rows x 16 k (row r at r*32, halves swizzled: half ^= (r>>2)&1)
// B tile: 16 k x 128 n (row k at k*256, granule g at ((g + k)&15)*16)
// ---------------------------------------------------------------------------
__device__ __align__(16) bf16 g_Xp   [512 * 64 * 4096];   // X: M=65536, K=1024
__device__ __align__(16) bf16 g_ATTp [512 * 64 * 4096];
__device__ __align__(16) bf16 g_COMPp[8 * 128 * 4096];    // M=1024, K=2048
__device__ __align__(16) bf16 g_HIDp [8 * 16 * 4096];     // M=1024, K=256
__device__ __align__(16) bf16 g_GENp [128 * 16 * 4096];   // M=16384, K=256
__device__ __align__(16) bf16 g_WqP  [8 * 64 * 4096];
__device__ __align__(16) bf16 g_WkP  [8 * 64 * 4096];
__device__ __align__(16) bf16 g_WvP  [8 * 64 * 4096];
__device__ __align__(16) bf16 g_WoP  [8 * 64 * 4096];
__device__ __align__(16) bf16 g_WgP  [32 * 16 * 4096];    // K=256, N=4096
__device__ __align__(16) bf16 g_Wd1P [2 * 128 * 4096];    // K=2048, N=256
__device__ __align__(16) bf16 g_Wd2P [32 * 16 * 4096];    // K=256, N=4096
__device__ __align__(16) bf16 g_WcP  [1 * 64 * 4096];     // K=1024, N=32 (pad 128)

__device__ __forceinline__ bf16* packSel(int i) {
    switch (i) {
        case 0: return g_Xp;   case 1: return g_ATTp; case 2: return g_COMPp;
        case 3: return g_HIDp; case 4: return g_GENp; case 5: return g_WqP;
        case 6: return g_WkP;  case 7: return g_WvP;  case 8: return g_WoP;
        case 9: return g_WgP;  case 10: return g_Wd1P; case 11: return g_Wd2P;
        default: return g_WcP;
    }
}

// ---------------------------------------------------------------------------
// PTX helpers
// ---------------------------------------------------------------------------
__device__ __forceinline__ u32 smem_u32(const void* p) {
    u32 a;
    asm("{ .reg .u64 t; cvta.to.shared.u64 t, %1; cvt.u32.u64 %0, t; }" : "=r"(a) : "l"(p));
    return a;
}
__device__ __forceinline__ void ldsm_x4(u32* r, u32 addr) {
    asm volatile("ldmatrix.sync.aligned.m8n8.x4.shared.b16 {%0,%1,%2,%3}, [%4];"
                 : "=r"(r[0]), "=r"(r[1]), "=r"(r[2]), "=r"(r[3]) : "r"(addr));
}
__device__ __forceinline__ void ldsm_x4_t(u32* r, u32 addr) {
    asm volatile("ldmatrix.sync.aligned.m8n8.x4.trans.shared.b16 {%0,%1,%2,%3}, [%4];"
                 : "=r"(r[0]), "=r"(r[1]), "=r"(r[2]), "=r"(r[3]) : "r"(addr));
}
__device__ __forceinline__ void mma_bf16(float* c, const u32* a, const u32* b) {
    asm volatile(
        "mma.sync.aligned.m16n8k16.row.col.f32.bf16.bf16.f32 "
        "{%0,%1,%2,%3}, {%4,%5,%6,%7}, {%8,%9}, {%0,%1,%2,%3};"
        : "+f"(c[0]), "+f"(c[1]), "+f"(c[2]), "+f"(c[3])
        : "r"(a[0]), "r"(a[1]), "r"(a[2]), "r"(a[3]), "r"(b[0]), "r"(b[1]));
}
#define MBAR_INIT(addr, cnt) \
    asm volatile("mbarrier.init.shared.b64 [%0], %1;" :: "r"(addr), "r"(cnt) : "memory")
#define MBAR_EXPECT_TX(addr, tx) \
    asm volatile("mbarrier.arrive.expect_tx.shared.b64 _, [%0], %1;" :: "r"(addr), "r"((u32)(tx)) : "memory")
#define MBAR_ARRIVE(addr) \
    asm volatile("mbarrier.arrive.release.cta.shared::cta.b64 _, [%0];" :: "r"(addr) : "memory")
#define MBAR_WAIT(addr, parity) do {                                           \
    u32 _m = (addr); u32 _p = (parity); u32 _done;                             \
    asm volatile("{\n\t.reg .pred p;\n\t"                                      \
        "mbarrier.try_wait.parity.acquire.cta.shared::cta.b64 p, [%1], %2;\n\t"\
        "selp.b32 %0, 1, 0, p;\n\t}" : "=r"(_done) : "r"(_m), "r"(_p) : "memory"); \
    if (!_done) {                                                              \
        asm volatile("{\n\t.reg .pred P1;\n\t"                                 \
            "WL_%=:\n\t"                                                       \
            "mbarrier.try_wait.parity.acquire.cta.shared::cta.b64 P1, [%0], %1, 0x989680;\n\t" \
            "@P1 bra.uni WD_%=;\n\t"                                           \
            "bra.uni WL_%=;\n\t"                                               \
            "WD_%=:\n\t}" :: "r"(_m), "r"(_p) : "memory");                     \
    } } while (0)
#define CP_BULK(dst, src, bytes, mbar) \
    asm volatile("cp.async.bulk.shared::cluster.global.mbarrier::complete_tx::bytes [%0], [%1], %2, [%3];" \
                 :: "r"(dst), "l"(src), "r"((u32)(bytes)), "r"(mbar) : "memory")

__device__ __forceinline__ void split2(float v0, float v1, __nv_bfloat162& h, __nv_bfloat162& l) {
    h = __floats2bfloat162_rn(v0, v1);
    l = __floats2bfloat162_rn(v0 - __bfloat162float(h.x), v1 - __bfloat162float(h.y));
}

// store an (even) column pair into a packed-A image
__device__ __forceinline__ void packA_store2(bf16* dst, int NCk, int rowA, int colA,
                                             float v0, float v1) {
    int rB = rowA >> 7, r = rowA & 127;
    int chunk = colA >> 4;
    int half = (colA >> 3) & 1;
    int halfS = half ^ ((r >> 2) & 1);
    size_t off = ((size_t)rB * NCk + chunk) * 8192 + r * 32 + (halfS << 4) + (colA & 7) * 2;
    __nv_bfloat162 h, l;
    split2(v0, v1, h, l);
    *(__nv_bfloat162*)((char*)dst + off)        = h;
    *(__nv_bfloat162*)((char*)dst + off + 4096) = l;
}

// ---------------------------------------------------------------------------
// prep_packA: fp32 row-major (M x Kd) -> packed hi/lo A image
// ---------------------------------------------------------------------------
__global__ __launch_bounds__(256) void prep_packA(
    const float* __restrict__ src, int dstSel, int M, int Kd)
{
    bf16* dst = packSel(dstSel);
    const int perRow = Kd >> 3;
    const int NCk = Kd >> 4;
    const int total = M * perRow;
    for (int gid = blockIdx.x * 256 + threadIdx.x; gid < total; gid += gridDim.x * 256) {
        int m = gid / perRow, gs = gid - m * perRow;
        int k0 = gs << 3;
        int chunk = k0 >> 4, half = (k0 >> 3) & 1;
        int rB = m >> 7, r = m & 127;
        int halfS = half ^ ((r >> 2) & 1);
        const float* s = src + (size_t)m * Kd + k0;
        float4 va = *(const float4*)s;
        float4 vb = *(const float4*)(s + 4);
        __nv_bfloat162 h0, l0, h1, l1, h2, l2, h3, l3;
        split2(va.x, va.y, h0, l0); split2(va.z, va.w, h1, l1);
        split2(vb.x, vb.y, h2, l2); split2(vb.z, vb.w, h3, l3);
        uint4 hv, lv;
        hv.x = *(u32*)&h0; hv.y = *(u32*)&h1; hv.z = *(u32*)&h2; hv.w = *(u32*)&h3;
        lv.x = *(u32*)&l0; lv.y = *(u32*)&l1; lv.z = *(u32*)&l2; lv.w = *(u32*)&l3;
        char* base = (char*)dst + ((size_t)rB * NCk + chunk) * 8192 + r * 32 + (halfS << 4);
        *(uint4*)base          = hv;
        *(uint4*)(base + 4096) = lv;
    }
}

// ---------------------------------------------------------------------------
// prep_packB: fp32 row-major (Kd x Nd) -> packed hi/lo B image (pad to NT*128)
// ---------------------------------------------------------------------------
__global__ __launch_bounds__(256) void prep_packB(
    const float* __restrict__ src, int dstSel, int Kd, int Nd, int NT)
{
    bf16* dst = packSel(dstSel);
    const int perRow = NT << 4;
    const int NCk = Kd >> 4;
    const int total = Kd * perRow;
    for (int gid = blockIdx.x * 256 + threadIdx.x; gid < total; gid += gridDim.x * 256) {
        int k = gid / perRow, gs = gid - k * perRow;
        int n0 = gs << 3;
        int nt = n0 >> 7, gg = (n0 >> 3) & 15;
        int pos = (gg + (k & 15)) & 15;
        float vv[8];
        #pragma unroll
        for (int j = 0; j < 8; j++) {
            int n = n0 + j;
            vv[j] = (n < Nd) ? src[(size_t)k * Nd + n] : 0.f;
        }
        __nv_bfloat162 h0, l0, h1, l1, h2, l2, h3, l3;
        split2(vv[0], vv[1], h0, l0); split2(vv[2], vv[3], h1, l1);
        split2(vv[4], vv[5], h2, l2); split2(vv[6], vv[7], h3, l3);
        uint4 hv, lv;
        hv.x = *(u32*)&h0; hv.y = *(u32*)&h1; hv.z = *(u32*)&h2; hv.w = *(u32*)&h3;
        lv.x = *(u32*)&l0; lv.y = *(u32*)&l1; lv.z = *(u32*)&l2; lv.w = *(u32*)&l3;
        char* base = (char*)dst + ((size_t)nt * NCk + (k >> 4)) * 8192 + (k & 15) * 256 + pos * 16;
        *(uint4*)base          = hv;
        *(uint4*)(base + 4096) = lv;
    }
}

// ---------------------------------------------------------------------------
// bulk_gemm: C = A @ B via split-bf16 HMMA. 4-stage cp.async.bulk pipeline
// with full/empty mbarriers — NO __syncthreads in mainloop (no convoy).
// Each warp: wait full[s] -> compute -> arrive empty[s]. tid0 additionally
// waits empty[s] (all 256 arrivals) before re-issuing stage s for chunk c+4.
// mode 0: fp32 row-major (+bias). mode 1: QKV scatter. mode 2: packed COMP.
// ---------------------------------------------------------------------------
__global__ __launch_bounds__(256, 2) void bulk_gemm(
    int aSel, int bSel,
    const float* __restrict__ b0p, const float* __restrict__ b1p,
    const float* __restrict__ b2p,
    float* __restrict__ Cout, int dstC, int NCk, int Nout, int mode)
{
    extern __shared__ __align__(128) unsigned char smp[];   // 4 x 16KB stages
    __shared__ __align__(8) u64 s_full[4];
    __shared__ __align__(8) u64 s_empty[4];

    const int tid = threadIdx.x;
    const int wid = tid >> 5, lane = tid & 31;
    const int wm = wid & 3, wn = wid >> 2;
    const int m0 = wm * 32;
    const int bx = blockIdx.x, by = blockIdx.y;

    const unsigned char* aPack = (const unsigned char*)packSel(aSel);
    const unsigned char* bPack;
    const float* bias;
    float* C = nullptr;
    int ntl;
    if (mode == 1) {
        int t = bx >> 3; ntl = bx & 7;
        bPack = (const unsigned char*)packSel(5 + t);
        bias = (t == 0) ? b0p : ((t == 1) ? b1p : b2p);
        C    = (t == 0) ? g_Q : ((t == 1) ? g_K : g_V);
    } else {
        bPack = (const unsigned char*)packSel(bSel);
        bias = b0p; ntl = bx;
        if (mode == 0) C = (dstC >= 0) ? scratch_ptr(dstC) : Cout;
    }

    const u32 smbase = smem_u32(smp);
    const u32 fbase  = smem_u32(&s_full[0]);
    const u32 ebase  = smem_u32(&s_empty[0]);

    if (tid == 0) {
        #pragma unroll
        for (int s = 0; s < 4; s++) {
            MBAR_INIT(fbase + s * 8, 1);
            MBAR_INIT(ebase + s * 8, 256);
        }
    }
    __syncthreads();

    const size_t aBase = (size_t)by * NCk * 8192;
    const size_t bBase = (size_t)ntl * NCk * 8192;

    // prologue: fill all 4 stages
    if (tid == 0) {
        #pragma unroll
        for (int c = 0; c < 4; c++) {
            if (c < NCk) {
                u32 fb = fbase + c * 8;
                u32 dst = smbase + c * 16384;
                MBAR_EXPECT_TX(fb, 16384);
                CP_BULK(dst,        aPack + aBase + (size_t)c * 8192, 8192, fb);
                CP_BULK(dst + 8192, bPack + bBase + (size_t)c * 8192, 8192, fb);
            }
        }
    }

    // lane addressing
    const int g = lane >> 3, r = lane & 7;
    const int a_row = ((g & 1) << 3) + r;
    const int halfA = g >> 1;
    const int b_row = ((g & 1) << 3) + r;
    const int b_gadd = g >> 1;

    float acc[2][8][4];
    #pragma unroll
    for (int mf = 0; mf < 2; mf++)
        #pragma unroll
        for (int nf = 0; nf < 8; nf++)
            #pragma unroll
            for (int i = 0; i < 4; i++) acc[mf][nf][i] = 0.f;

    auto compute_chunk = [&](u32 stb) {
        u32 afh[2][4], afl[2][4];
        #pragma unroll
        for (int mf = 0; mf < 2; mf++) {
            int R = m0 + mf * 16 + a_row;
            u32 aoff = R * 32 + (((u32)halfA ^ ((R >> 2) & 1)) << 4);
            ldsm_x4(afh[mf], stb + aoff);
            ldsm_x4(afl[mf], stb + 4096 + aoff);
        }
        #pragma unroll
        for (int nf2 = 0; nf2 < 4; nf2++) {
            int g16 = wn * 8 + nf2 * 2 + b_gadd;
            u32 boff = b_row * 256 + (((g16 + b_row) & 15) << 4);
            u32 bh4[4], bl4[4];
            ldsm_x4_t(bh4, stb + 8192  + boff);
            ldsm_x4_t(bl4, stb + 12288 + boff);
            #pragma unroll
            for (int mf = 0; mf < 2; mf++) {
                mma_bf16(acc[mf][nf2 * 2 + 0], afh[mf], bh4 + 0);
                mma_bf16(acc[mf][nf2 * 2 + 1], afh[mf], bh4 + 2);
                mma_bf16(acc[mf][nf2 * 2 + 0], afh[mf], bl4 + 0);
                mma_bf16(acc[mf][nf2 * 2 + 1], afh[mf], bl4 + 2);
                mma_bf16(acc[mf][nf2 * 2 + 0], afl[mf], bh4 + 0);
                mma_bf16(acc[mf][nf2 * 2 + 1], afl[mf], bh4 + 2);
            }
        }
    };

    for (int c = 0; c < NCk; c++) {
        const int s = c & 3;
        const u32 ph = (u32)(c >> 2) & 1u;
        MBAR_WAIT(fbase + s * 8, ph);
        compute_chunk(smbase + s * 16384);
        MBAR_ARRIVE(ebase + s * 8);
        if (tid == 0) {
            int cn = c + 4;
            if (cn < NCk) {
                // wait until ALL warps have consumed stage s (chunk c)
                MBAR_WAIT(ebase + s * 8, ph);
                u32 fb = fbase + s * 8;
                u32 dst = smbase + s * 16384;
                MBAR_EXPECT_TX(fb, 16384);
                CP_BULK(dst,        aPack + aBase + (size_t)cn * 8192, 8192, fb);
                CP_BULK(dst + 8192, bPack + bBase + (size_t)cn * 8192, 8192, fb);
            }
        }
    }

    // ---- epilogue (accs are register-private; no sync needed) ----
    #pragma unroll
    for (int mf = 0; mf < 2; mf++) {
        #pragma unroll
        for (int nf = 0; nf < 8; nf++) {
            int mrow = by * 128 + m0 + mf * 16 + (lane >> 2);
            int ncol = ntl * 128 + wn * 64 + nf * 8 + (lane & 3) * 2;
            float bv0 = bias ? bias[ncol] : 0.f;
            float bv1 = bias ? bias[ncol + 1] : 0.f;
            #pragma unroll
            for (int half = 0; half < 2; half++) {
                int mr = mrow + half * 8;
                float v0 = acc[mf][nf][half * 2 + 0] + bv0;
                float v1 = acc[mf][nf][half * 2 + 1] + bv1;
                if (mode == 1) {
                    int bb = mr >> 6, ss = mr & 63;
                    int h = ncol >> 6, d = ncol & 63;
                    float* p = C + ((((size_t)bb * NH + h) * SEQ + ss) * HD) + d;
                    p[0] = v0; p[1] = v1;
                } else if (mode == 0) {
                    float* p = C + (size_t)mr * Nout + ncol;
                    *(float2*)p = make_float2(v0, v1);
                } else {
                    if (ncol < HC)
                        packA_store2(g_COMPp, 128, mr >> 6, ((mr & 63) << 5) + ncol, v0, v1);
                }
            }
        }
    }
}

// ---------------------------------------------------------------------------
// silu + LN -> packed-A image (layout 1: colA=i; layout 2: rowA=row*16+(i>>8))
// ---------------------------------------------------------------------------
__global__ __launch_bounds__(256) void silu_ln_kernel(
    const float* __restrict__ g, const float* __restrict__ be,
    int N, int srcIdx, int outSel, int NCkOut, int layout)
{
    const float* in = scratch_ptr(srcIdx);
    bf16* outp = packSel(outSel);

    __shared__ float hs[4096];
    __shared__ float red[2][8];

    const int row = blockIdx.x;
    const int tid = threadIdx.x;
    const float* pin = in + (size_t)row * N;

    float sum = 0.f, sq = 0.f;
    for (int i = tid; i < N; i += 256) {
        float y = pin[i];
        float h = y / (1.f + expf(-y));
        hs[i] = h;
        sum += h;
        sq  += h * h;
    }
    #pragma unroll
    for (int off = 16; off > 0; off >>= 1) {
        sum += __shfl_xor_sync(0xffffffffu, sum, off);
        sq  += __shfl_xor_sync(0xffffffffu, sq,  off);
    }
    if ((tid & 31) == 0) { red[0][tid >> 5] = sum; red[1][tid >> 5] = sq; }
    __syncthreads();
    if (tid < 32) {
        float s = (tid < 8) ? red[0][tid] : 0.f;
        float q = (tid < 8) ? red[1][tid] : 0.f;
        #pragma unroll
        for (int off = 4; off > 0; off >>= 1) {
            s += __shfl_xor_sync(0xffffffffu, s, off);
            q += __shfl_xor_sync(0xffffffffu, q, off);
        }
        if (tid == 0) { red[0][0] = s; red[1][0] = q; }
    }
    __syncthreads();
    const float mean = red[0][0] / (float)N;
    const float var  = red[1][0] / (float)N - mean * mean;
    const float inv  = rsqrtf(var + LN_EPS);

    for (int i = tid * 2; i < N; i += 512) {
        float v0 = (hs[i] - mean) * inv * g[i] + be[i];
        float v1 = (hs[i + 1] - mean) * inv * g[i + 1] + be[i + 1];
        int rowA, colA;
        if (layout == 1) { rowA = row; colA = i; }
        else             { rowA = row * 16 + (i >> 8); colA = i & 255; }
        packA_store2(outp, NCkOut, rowA, colA, v0, v1);
    }
}

// ---------------------------------------------------------------------------
// Attention: softmax(q@k^T*scale + bias) @ v -> packed ATT image directly
// ---------------------------------------------------------------------------
__global__ __launch_bounds__(256) void attn_kernel()
{
    __shared__ float ks[64][65];
    __shared__ float vs[64][65];
    __shared__ float ps[8][64];

    const int bh = blockIdx.x;
    const int b = bh >> 4, h = bh & 15;
    const int tid = threadIdx.x;
    const float* kp = g_K + (size_t)bh * (SEQ * HD);
    const float* vp = g_V + (size_t)bh * (SEQ * HD);
    const float* qp = g_Q + (size_t)bh * (SEQ * HD);
    const float* bp = g_BIAS + (size_t)bh * (SEQ * SEQ);

    #pragma unroll
    for (int p = 0; p < 4; p++) {
        int idx = tid + 256 * p;
        int s = idx >> 4, d4 = (idx & 15) * 4;
        float4 kv = *(const float4*)(kp + s * HD + d4);
        ks[s][d4] = kv.x; ks[s][d4 + 1] = kv.y; ks[s][d4 + 2] = kv.z; ks[s][d4 + 3] = kv.w;
        float4 vv = *(const float4*)(vp + s * HD + d4);
        vs[s][d4] = vv.x; vs[s][d4 + 1] = vv.y; vs[s][d4 + 2] = vv.z; vs[s][d4 + 3] = vv.w;
    }
    __syncthreads();

    const int w = tid >> 5, lane = tid & 31;
    const float scale = 0.125f;

    for (int rr = w * 8; rr < w * 8 + 8; rr++) {
        const float* q = qp + rr * HD;
        float dot0 = 0.f, dot1 = 0.f;
        #pragma unroll
        for (int k = 0; k < 64; k++) {
            float qk = __ldg(q + k);
            dot0 += qk * ks[lane][k];
            dot1 += qk * ks[lane + 32][k];
        }
        float acc0 = dot0 * scale + bp[rr * 64 + lane];
        float acc1 = dot1 * scale + bp[rr * 64 + lane + 32];

        float m = fmaxf(acc0, acc1);
        #pragma unroll
        for (int off = 16; off > 0; off >>= 1)
            m = fmaxf(m, __shfl_xor_sync(0xffffffffu, m, off));
        float e0 = __expf(acc0 - m), e1 = __expf(acc1 - m);
        float s = e0 + e1;
        #pragma unroll
        for (int off = 16; off > 0; off >>= 1)
            s += __shfl_xor_sync(0xffffffffu, s, off);
        float invs = 1.f / s;

        __syncwarp();
        ps[w][lane]      = e0 * invs;
        ps[w][lane + 32] = e1 * invs;
        __syncwarp();

        // AV: each lane produces adjacent column pair (2*lane, 2*lane+1)
        float o0 = 0.f, o1 = 0.f;
        #pragma unroll
        for (int j = 0; j < 64; j++) {
            float pj = ps[w][j];
            o0 += pj * vs[j][2 * lane];
            o1 += pj * vs[j][2 * lane + 1];
        }
        packA_store2(g_ATTp, 64, b * SEQ + rr, h * HD + 2 * lane, o0, o1);
    }
}

// ---------------------------------------------------------------------------
// kernel_launch
// ---------------------------------------------------------------------------
extern "C" void kernel_launch(void* const* d_in, const int* in_sizes, int n_in,
                              void* d_out, int out_size)
{
    const float* x   = (const float*)d_in[0];
    const float* Wq  = (const float*)d_in[1];
    const float* bq  = (const float*)d_in[2];
    const float* Wk  = (const float*)d_in[3];
    const float* bk  = (const float*)d_in[4];
    const float* Wv  = (const float*)d_in[5];
    const float* bv  = (const float*)d_in[6];
    const float* Wo  = (const float*)d_in[7];
    const float* bo  = (const float*)d_in[8];
    const float* Wc  = (const float*)d_in[9];
    const float* Wd1 = (const float*)d_in[10];
    const float* bd1 = (const float*)d_in[11];
    const float* g1  = (const float*)d_in[12];
    const float* be1 = (const float*)d_in[13];
    const float* Wd2 = (const float*)d_in[14];
    const float* bd2 = (const float*)d_in[15];
    const float* g2  = (const float*)d_in[16];
    const float* be2 = (const float*)d_in[17];
    const float* Wg  = (const float*)d_in[18];

    cudaFuncSetAttribute(bulk_gemm, cudaFuncAttributeMaxDynamicSharedMemorySize, 65536);

    // ---- packing ----
    prep_packA<<<4096, 256>>>(x, 0, BATCH * SEQ, EMB);
    prep_packB<<<128, 256>>>(Wq,  5, EMB, EMB, 8);
    prep_packB<<<128, 256>>>(Wk,  6, EMB, EMB, 8);
    prep_packB<<<128, 256>>>(Wv,  7, EMB, EMB, 8);
    prep_packB<<<128, 256>>>(Wo,  8, EMB, EMB, 8);
    prep_packB<<<64,  256>>>(Wg,  9, GS, SEQ * SEQ, 32);
    prep_packB<<<64,  256>>>(Wd1, 10, SEQ * HC, HS, 2);
    prep_packB<<<64,  256>>>(Wd2, 11, HS, GS * NH, 32);
    prep_packB<<<32,  256>>>(Wc,  12, EMB, HC, 1);

    // ---- QKV fused (mode 1) ----
    bulk_gemm<<<dim3(24, 512), 256, 65536>>>(
        0, -1, bq, bk, bv, nullptr, -1, 64, EMB, 1);

    // ---- compress (mode 2 -> packed COMP) ----
    bulk_gemm<<<dim3(1, 512), 256, 65536>>>(
        0, 12, nullptr, nullptr, nullptr, nullptr, -1, 64, HC, 2);

    // ---- dense1 -> g_T1 fp32 ----
    bulk_gemm<<<dim3(2, 8), 256, 65536>>>(
        2, 10, bd1, nullptr, nullptr, nullptr, 3, 128, HS, 0);
    silu_ln_kernel<<<BATCH, 256>>>(g1, be1, HS, 3, 3, 16, 1);

    // ---- dense2 -> g_T2 fp32 ----
    bulk_gemm<<<dim3(32, 8), 256, 65536>>>(
        3, 11, bd2, nullptr, nullptr, nullptr, 4, 16, GS * NH, 0);
    silu_ln_kernel<<<BATCH, 256>>>(g2, be2, GS * NH, 4, 4, 16, 2);

    // ---- bias-gen -> g_BIAS fp32 ----
    bulk_gemm<<<dim3(32, 128), 256, 65536>>>(
        4, 9, nullptr, nullptr, nullptr, nullptr, 5, 16, SEQ * SEQ, 0);

    // ---- attention -> packed ATT directly ----
    attn_kernel<<<BATCH * NH, 256>>>();

    // ---- output projection -> d_out ----
    bulk_gemm<<<dim3(8, 512), 256, 65536>>>(
        1, 8, bo, nullptr, nullptr, (float*)d_out, -1, 64, EMB, 0);
}